// round 3
// baseline (speedup 1.0000x reference)
#include <cuda_runtime.h>
#include <stdint.h>

#define BSZ  4
#define QLEN 2048
#define DIM  1024
#define NH   16
#define DH   64
#define MTOT (BSZ * QLEN)   // 8192

// Scratch (allocation-free rule: __device__ globals)
__device__ float g_q[BSZ * NH * QLEN * DH];
__device__ float g_k[BSZ * NH * QLEN * DH];
__device__ float g_v[BSZ * NH * QLEN * DH];
__device__ float g_ctx[MTOT * DIM];

__device__ __forceinline__ uint32_t f2tf(float f) {
    uint32_t r;
    asm("cvt.rna.tf32.f32 %0, %1;" : "=r"(r) : "f"(f));
    return r;
}

// D = A(16x8,row) * B(8x8,col) + D, tf32, fp32 accum
__device__ __forceinline__ void mma8(float c[4], const uint32_t a[4], const uint32_t b[2]) {
    asm volatile(
        "mma.sync.aligned.m16n8k8.row.col.f32.tf32.tf32.f32 "
        "{%0,%1,%2,%3}, {%4,%5,%6,%7}, {%8,%9}, {%0,%1,%2,%3};\n"
        : "+f"(c[0]), "+f"(c[1]), "+f"(c[2]), "+f"(c[3])
        : "r"(a[0]), "r"(a[1]), "r"(a[2]), "r"(a[3]), "r"(b[0]), "r"(b[1]));
}

// ---------------------------------------------------------------------------
// GEMM body: C = A[MTOT,1024] @ W[1024,1024]^T (+ bias) (* scale)
// BM=128, BN=128, BK=16, 256 threads, 8 warps (2m x 4n), warp tile 64x32.
// ---------------------------------------------------------------------------
#define SKA 20   // smem k-stride (16 + 4 pad) -> conflict-free frag loads

__device__ __forceinline__ void gemm_body(
    uint32_t* As, uint32_t* Bs,          // [2][128*SKA] each
    const float* __restrict__ A, const float* __restrict__ W,
    const float* __restrict__ bias, float* __restrict__ out,
    float scale, int scatter)
{
    const int m0 = blockIdx.y * 128, n0 = blockIdx.x * 128;
    const int tid = threadIdx.x, lane = tid & 31, wid = tid >> 5;
    const int wm = (wid >> 2) * 64, wn = (wid & 3) * 32;
    const int g = lane >> 2, t = lane & 3;

    const int arow0 = tid >> 2;          // rows arow0, arow0+64
    const int ac4   = (tid & 3) * 4;

    float4 pa[2], pw[2];
    #pragma unroll
    for (int l = 0; l < 2; l++) {
        int row = arow0 + l * 64;
        pa[l] = *(const float4*)&A[(size_t)(m0 + row) * DIM + ac4];
        pw[l] = *(const float4*)&W[(size_t)(n0 + row) * DIM + ac4];
    }
    #pragma unroll
    for (int l = 0; l < 2; l++) {
        int row = arow0 + l * 64;
        uint32_t* p = &As[row * SKA + ac4];
        p[0] = f2tf(pa[l].x); p[1] = f2tf(pa[l].y); p[2] = f2tf(pa[l].z); p[3] = f2tf(pa[l].w);
        uint32_t* q = &Bs[row * SKA + ac4];
        q[0] = f2tf(pw[l].x); q[1] = f2tf(pw[l].y); q[2] = f2tf(pw[l].z); q[3] = f2tf(pw[l].w);
    }

    float c[4][4][4] = {};

    #pragma unroll 1
    for (int kt = 0; kt < DIM / 16; kt++) {
        const int buf = (kt & 1) * 128 * SKA;
        __syncthreads();
        if (kt + 1 < DIM / 16) {
            const int k0 = (kt + 1) * 16;
            #pragma unroll
            for (int l = 0; l < 2; l++) {
                int row = arow0 + l * 64;
                pa[l] = *(const float4*)&A[(size_t)(m0 + row) * DIM + k0 + ac4];
                pw[l] = *(const float4*)&W[(size_t)(n0 + row) * DIM + k0 + ac4];
            }
        }
        #pragma unroll
        for (int ks = 0; ks < 2; ks++) {
            const int kb = ks * 8;
            uint32_t af[4][4], bf[4][2];
            #pragma unroll
            for (int mt = 0; mt < 4; mt++) {
                int r = wm + mt * 16;
                const uint32_t* p0 = &As[buf + (r + g) * SKA + kb + t];
                const uint32_t* p1 = &As[buf + (r + g + 8) * SKA + kb + t];
                af[mt][0] = p0[0]; af[mt][1] = p1[0];
                af[mt][2] = p0[4]; af[mt][3] = p1[4];
            }
            #pragma unroll
            for (int nt = 0; nt < 4; nt++) {
                int n = wn + nt * 8;
                const uint32_t* p = &Bs[buf + (n + g) * SKA + kb + t];
                bf[nt][0] = p[0]; bf[nt][1] = p[4];
            }
            #pragma unroll
            for (int mt = 0; mt < 4; mt++)
                #pragma unroll
                for (int nt = 0; nt < 4; nt++)
                    mma8(c[mt][nt], af[mt], bf[nt]);
        }
        if (kt + 1 < DIM / 16) {
            const int nbuf = ((kt + 1) & 1) * 128 * SKA;
            #pragma unroll
            for (int l = 0; l < 2; l++) {
                int row = arow0 + l * 64;
                uint32_t* p = &As[nbuf + row * SKA + ac4];
                p[0] = f2tf(pa[l].x); p[1] = f2tf(pa[l].y); p[2] = f2tf(pa[l].z); p[3] = f2tf(pa[l].w);
                uint32_t* q = &Bs[nbuf + row * SKA + ac4];
                q[0] = f2tf(pw[l].x); q[1] = f2tf(pw[l].y); q[2] = f2tf(pw[l].z); q[3] = f2tf(pw[l].w);
            }
        }
    }

    // Epilogue
    #pragma unroll
    for (int mt = 0; mt < 4; mt++) {
        #pragma unroll
        for (int nt = 0; nt < 4; nt++) {
            const int n = n0 + wn + nt * 8 + 2 * t;
            const float2 bb = *(const float2*)&bias[n];
            #pragma unroll
            for (int rr = 0; rr < 2; rr++) {
                const int m = m0 + wm + mt * 16 + g + rr * 8;
                float2 v;
                v.x = (c[mt][nt][rr * 2 + 0] + bb.x) * scale;
                v.y = (c[mt][nt][rr * 2 + 1] + bb.y) * scale;
                if (scatter) {
                    int b = m >> 11, ts = m & 2047;
                    int h = n >> 6, d = n & 63;
                    *(float2*)&out[(size_t)(((b * NH + h) * QLEN) + ts) * DH + d] = v;
                } else {
                    *(float2*)&out[(size_t)m * DIM + n] = v;
                }
            }
        }
    }
}

// Fused QKV projection: grid.z selects {Q,K,V}
__global__ __launch_bounds__(256, 2) void gemm_qkv(
    const float* __restrict__ x,
    const float* __restrict__ wq, const float* __restrict__ bq,
    const float* __restrict__ wk, const float* __restrict__ bk,
    const float* __restrict__ wv, const float* __restrict__ bv,
    float* __restrict__ qp, float* __restrict__ kp, float* __restrict__ vp)
{
    __shared__ uint32_t As[2 * 128 * SKA];
    __shared__ uint32_t Bs[2 * 128 * SKA];
    const int z = blockIdx.z;
    const float* W = (z == 0) ? wq : (z == 1) ? wk : wv;
    const float* B = (z == 0) ? bq : (z == 1) ? bk : bv;
    float* out     = (z == 0) ? qp : (z == 1) ? kp : vp;
    const float scale = (z == 0) ? 0.125f : 1.0f;
    gemm_body(As, Bs, x, W, B, out, scale, 1);
}

__global__ __launch_bounds__(256, 2) void gemm_out(
    const float* __restrict__ A, const float* __restrict__ W,
    const float* __restrict__ bias, float* __restrict__ out)
{
    __shared__ uint32_t As[2 * 128 * SKA];
    __shared__ uint32_t Bs[2 * 128 * SKA];
    gemm_body(As, Bs, A, W, bias, out, 1.0f, 0);
}

// ---------------------------------------------------------------------------
// Flash attention, tf32 tensor cores.
// Block: 128 queries, 8 warps (warp = 16q x 64k), loop over 64-key tiles.
// Q fragments register-resident (staged once via Ps).
// Smem (u32 words): Ks 64x68, Vs 64x72, Ps 128x68, mb 64.
// ---------------------------------------------------------------------------
#define SKK 68
#define SKV 72
#define SKP 68
#define AOFF_K 0
#define AOFF_V (64 * SKK)                 // 4352
#define AOFF_P (AOFF_V + 64 * SKV)        // 8960
#define AOFF_MB (AOFF_P + 128 * SKP)      // 17664
#define ATTN_WORDS (AOFF_MB + 64)         // 17728
#define ATTN_SMEM_BYTES (ATTN_WORDS * 4)  // 70912

__global__ __launch_bounds__(256, 2) void attn_tf32(const int* __restrict__ mask)
{
    extern __shared__ uint32_t sm[];
    uint32_t* Ks = sm + AOFF_K;
    uint32_t* Vs = sm + AOFF_V;
    uint32_t* Ps = sm + AOFF_P;
    float*    mb = (float*)(sm + AOFF_MB);

    const int bh = blockIdx.y, b = bh >> 4, h = bh & 15;
    const int q0 = blockIdx.x * 128;
    const int tid = threadIdx.x, lane = tid & 31, wid = tid >> 5;
    const int g = lane >> 2, t = lane & 3;
    const int qw = wid * 16;

    const float* Qg = g_q + (size_t)bh * QLEN * DH;
    const float* Kg = g_k + (size_t)bh * QLEN * DH;
    const float* Vg = g_v + (size_t)bh * QLEN * DH;

    // Stage Q tile (128x64) through Ps, then pull fragments to registers.
    #pragma unroll
    for (int l = 0; l < 8; l++) {
        int idx = tid + l * 256;
        int row = idx >> 4, c4 = (idx & 15) * 4;
        float4 v = *(const float4*)&Qg[(size_t)(q0 + row) * DH + c4];
        uint2 u0, u1;
        u0.x = f2tf(v.x); u0.y = f2tf(v.y);
        u1.x = f2tf(v.z); u1.y = f2tf(v.w);
        *(uint2*)&Ps[row * SKP + c4]     = u0;
        *(uint2*)&Ps[row * SKP + c4 + 2] = u1;
    }
    __syncthreads();
    uint32_t qf[8][4];
    #pragma unroll
    for (int ks = 0; ks < 8; ks++) {
        const uint32_t* p0 = &Ps[(qw + g) * SKP + ks * 8 + t];
        const uint32_t* p1 = &Ps[(qw + g + 8) * SKP + ks * 8 + t];
        qf[ks][0] = p0[0]; qf[ks][1] = p1[0];
        qf[ks][2] = p0[4]; qf[ks][3] = p1[4];
    }
    // (Ps rows are warp-private from here on: no cross-warp hazard.)

    float o[8][4] = {};
    float rm[2] = {-1e30f, -1e30f}, rl[2] = {0.0f, 0.0f};

    #pragma unroll 1
    for (int kt = 0; kt < QLEN / 64; kt++) {
        const int kbase = kt * 64;
        __syncthreads();   // prior tile's QK/PV reads of Ks/Vs complete
        #pragma unroll
        for (int l = 0; l < 4; l++) {
            int idx = tid + l * 256;
            int row = idx >> 4, c4 = (idx & 15) * 4;
            float4 kv = *(const float4*)&Kg[(size_t)(kbase + row) * DH + c4];
            uint2 ku0, ku1;
            ku0.x = f2tf(kv.x); ku0.y = f2tf(kv.y);
            ku1.x = f2tf(kv.z); ku1.y = f2tf(kv.w);
            *(uint2*)&Ks[row * SKK + c4]     = ku0;
            *(uint2*)&Ks[row * SKK + c4 + 2] = ku1;
            float4 vv = *(const float4*)&Vg[(size_t)(kbase + row) * DH + c4];
            uint4 vu;
            vu.x = f2tf(vv.x); vu.y = f2tf(vv.y); vu.z = f2tf(vv.z); vu.w = f2tf(vv.w);
            *(uint4*)&Vs[row * SKV + c4] = vu;
        }
        if (tid < 64)
            mb[tid] = (mask[b * QLEN + kbase + tid] == 0) ? -1e30f : 0.0f;
        __syncthreads();

        // S = Q @ K^T  (warp: 16q x 64k)
        float s[8][4] = {};
        #pragma unroll
        for (int ks = 0; ks < 8; ks++) {
            const int kb = ks * 8;
            #pragma unroll
            for (int nt = 0; nt < 8; nt++) {
                uint32_t bf[2];
                const uint32_t* p = &Ks[(nt * 8 + g) * SKK + kb + t];
                bf[0] = p[0]; bf[1] = p[4];
                mma8(s[nt], qf[ks], bf);
            }
        }

        // mask add
        #pragma unroll
        for (int nt = 0; nt < 8; nt++) {
            float b0 = mb[nt * 8 + 2 * t];
            float b1 = mb[nt * 8 + 2 * t + 1];
            s[nt][0] += b0; s[nt][1] += b1;
            s[nt][2] += b0; s[nt][3] += b1;
        }

        // online softmax (two row groups: g and g+8)
        #pragma unroll
        for (int r = 0; r < 2; r++) {
            float mx = -1e30f;
            #pragma unroll
            for (int nt = 0; nt < 8; nt++)
                mx = fmaxf(mx, fmaxf(s[nt][r * 2], s[nt][r * 2 + 1]));
            mx = fmaxf(mx, __shfl_xor_sync(0xffffffffu, mx, 1));
            mx = fmaxf(mx, __shfl_xor_sync(0xffffffffu, mx, 2));
            float mnew  = fmaxf(rm[r], mx);
            float alpha = __expf(rm[r] - mnew);
            rm[r] = mnew;
            float rs = 0.0f;
            #pragma unroll
            for (int nt = 0; nt < 8; nt++) {
                float p0 = __expf(s[nt][r * 2]     - mnew);
                float p1 = __expf(s[nt][r * 2 + 1] - mnew);
                s[nt][r * 2] = p0; s[nt][r * 2 + 1] = p1;
                rs += p0 + p1;
            }
            rs += __shfl_xor_sync(0xffffffffu, rs, 1);
            rs += __shfl_xor_sync(0xffffffffu, rs, 2);
            rl[r] = rl[r] * alpha + rs;
            #pragma unroll
            for (int nt = 0; nt < 8; nt++) {
                o[nt][r * 2]     *= alpha;
                o[nt][r * 2 + 1] *= alpha;
            }
        }

        // P -> smem (warp-private rows)
        #pragma unroll
        for (int nt = 0; nt < 8; nt++) {
            Ps[(qw + g) * SKP     + nt * 8 + 2 * t]     = f2tf(s[nt][0]);
            Ps[(qw + g) * SKP     + nt * 8 + 2 * t + 1] = f2tf(s[nt][1]);
            Ps[(qw + g + 8) * SKP + nt * 8 + 2 * t]     = f2tf(s[nt][2]);
            Ps[(qw + g + 8) * SKP + nt * 8 + 2 * t + 1] = f2tf(s[nt][3]);
        }
        __syncwarp();

        // O += P @ V
        #pragma unroll
        for (int ks = 0; ks < 8; ks++) {
            const int kb = ks * 8;
            uint32_t af[4];
            const uint32_t* p0 = &Ps[(qw + g) * SKP + kb + t];
            const uint32_t* p1 = &Ps[(qw + g + 8) * SKP + kb + t];
            af[0] = p0[0]; af[1] = p1[0]; af[2] = p0[4]; af[3] = p1[4];
            #pragma unroll
            for (int nt = 0; nt < 8; nt++) {
                uint32_t bf[2];
                bf[0] = Vs[(kb + t) * SKV + nt * 8 + g];
                bf[1] = Vs[(kb + t + 4) * SKV + nt * 8 + g];
                mma8(o[nt], af, bf);
            }
        }
    }

    // Epilogue: ctx[b, t, h*64 + d]
    #pragma unroll
    for (int r = 0; r < 2; r++) {
        float inv = 1.0f / rl[r];
        int row = q0 + qw + g + r * 8;
        #pragma unroll
        for (int nt = 0; nt < 8; nt++) {
            float2 v;
            v.x = o[nt][r * 2]     * inv;
            v.y = o[nt][r * 2 + 1] * inv;
            *(float2*)&g_ctx[(size_t)(b * QLEN + row) * DIM + h * DH + nt * 8 + 2 * t] = v;
        }
    }
}

// ---------------------------------------------------------------------------
extern "C" void kernel_launch(void* const* d_in, const int* in_sizes, int n_in,
                              void* d_out, int out_size)
{
    const float* x    = (const float*)d_in[0];
    const int*   mask = (const int*)  d_in[1];
    const float* wq   = (const float*)d_in[2];
    const float* bq   = (const float*)d_in[3];
    const float* wk   = (const float*)d_in[4];
    const float* bk   = (const float*)d_in[5];
    const float* wv   = (const float*)d_in[6];
    const float* bv   = (const float*)d_in[7];
    const float* wo   = (const float*)d_in[8];
    const float* bo   = (const float*)d_in[9];
    float* out = (float*)d_out;

    float *qp, *kp, *vp, *cp;
    cudaGetSymbolAddress((void**)&qp, g_q);
    cudaGetSymbolAddress((void**)&kp, g_k);
    cudaGetSymbolAddress((void**)&vp, g_v);
    cudaGetSymbolAddress((void**)&cp, g_ctx);

    cudaFuncSetAttribute(attn_tf32,
                         cudaFuncAttributeMaxDynamicSharedMemorySize,
                         ATTN_SMEM_BYTES);

    dim3 gq(DIM / 128, MTOT / 128, 3);
    gemm_qkv<<<gq, 256>>>(x, wq, bq, wk, bk, wv, bv, qp, kp, vp);

    dim3 ga(QLEN / 128, BSZ * NH);
    attn_tf32<<<ga, 256, ATTN_SMEM_BYTES>>>(mask);

    dim3 go(DIM / 128, MTOT / 128);
    gemm_out<<<go, 256>>>(cp, wo, bo, out);
}

// round 5
// speedup vs baseline: 1.0934x; 1.0934x over previous
#include <cuda_runtime.h>
#include <stdint.h>

#define BSZ  4
#define QLEN 2048
#define DIM  1024
#define NH   16
#define DH   64
#define MTOT (BSZ * QLEN)   // 8192

// Scratch (allocation-free rule: __device__ globals)
__device__ float g_q[BSZ * NH * QLEN * DH];
__device__ float g_k[BSZ * NH * QLEN * DH];
__device__ float g_v[BSZ * NH * QLEN * DH];
__device__ float g_ctx[MTOT * DIM];

__device__ __forceinline__ uint32_t f2tf(float f) {
    uint32_t r;
    asm("cvt.rna.tf32.f32 %0, %1;" : "=r"(r) : "f"(f));
    return r;
}

// D = A(16x8,row) * B(8x8,col) + D, tf32, fp32 accum
__device__ __forceinline__ void mma8(float c[4], const uint32_t a[4], const uint32_t b[2]) {
    asm volatile(
        "mma.sync.aligned.m16n8k8.row.col.f32.tf32.tf32.f32 "
        "{%0,%1,%2,%3}, {%4,%5,%6,%7}, {%8,%9}, {%0,%1,%2,%3};\n"
        : "+f"(c[0]), "+f"(c[1]), "+f"(c[2]), "+f"(c[3])
        : "r"(a[0]), "r"(a[1]), "r"(a[2]), "r"(a[3]), "r"(b[0]), "r"(b[1]));
}

// ---------------------------------------------------------------------------
// GEMM body: C = A[MTOT,1024] @ W[1024,1024]^T (+ bias) (* scale)
// BM=128, BN=128, BK=16, 256 threads, 8 warps (2m x 4n), warp tile 64x32.
// (proven round-2/3 version)
// ---------------------------------------------------------------------------
#define SKA 20   // smem k-stride (16 + 4 pad) -> conflict-free frag loads

__device__ __forceinline__ void gemm_body(
    uint32_t* As, uint32_t* Bs,          // [2][128*SKA] each
    const float* __restrict__ A, const float* __restrict__ W,
    const float* __restrict__ bias, float* __restrict__ out,
    float scale, int scatter)
{
    const int m0 = blockIdx.y * 128, n0 = blockIdx.x * 128;
    const int tid = threadIdx.x, lane = tid & 31, wid = tid >> 5;
    const int wm = (wid >> 2) * 64, wn = (wid & 3) * 32;
    const int g = lane >> 2, t = lane & 3;

    const int arow0 = tid >> 2;          // rows arow0, arow0+64
    const int ac4   = (tid & 3) * 4;

    float4 pa[2], pw[2];
    #pragma unroll
    for (int l = 0; l < 2; l++) {
        int row = arow0 + l * 64;
        pa[l] = *(const float4*)&A[(size_t)(m0 + row) * DIM + ac4];
        pw[l] = *(const float4*)&W[(size_t)(n0 + row) * DIM + ac4];
    }
    #pragma unroll
    for (int l = 0; l < 2; l++) {
        int row = arow0 + l * 64;
        uint32_t* p = &As[row * SKA + ac4];
        p[0] = f2tf(pa[l].x); p[1] = f2tf(pa[l].y); p[2] = f2tf(pa[l].z); p[3] = f2tf(pa[l].w);
        uint32_t* q = &Bs[row * SKA + ac4];
        q[0] = f2tf(pw[l].x); q[1] = f2tf(pw[l].y); q[2] = f2tf(pw[l].z); q[3] = f2tf(pw[l].w);
    }

    float c[4][4][4] = {};

    #pragma unroll 1
    for (int kt = 0; kt < DIM / 16; kt++) {
        const int buf = (kt & 1) * 128 * SKA;
        __syncthreads();
        if (kt + 1 < DIM / 16) {
            const int k0 = (kt + 1) * 16;
            #pragma unroll
            for (int l = 0; l < 2; l++) {
                int row = arow0 + l * 64;
                pa[l] = *(const float4*)&A[(size_t)(m0 + row) * DIM + k0 + ac4];
                pw[l] = *(const float4*)&W[(size_t)(n0 + row) * DIM + k0 + ac4];
            }
        }
        #pragma unroll
        for (int ks = 0; ks < 2; ks++) {
            const int kb = ks * 8;
            uint32_t af[4][4], bf[4][2];
            #pragma unroll
            for (int mt = 0; mt < 4; mt++) {
                int r = wm + mt * 16;
                const uint32_t* p0 = &As[buf + (r + g) * SKA + kb + t];
                const uint32_t* p1 = &As[buf + (r + g + 8) * SKA + kb + t];
                af[mt][0] = p0[0]; af[mt][1] = p1[0];
                af[mt][2] = p0[4]; af[mt][3] = p1[4];
            }
            #pragma unroll
            for (int nt = 0; nt < 4; nt++) {
                int n = wn + nt * 8;
                const uint32_t* p = &Bs[buf + (n + g) * SKA + kb + t];
                bf[nt][0] = p[0]; bf[nt][1] = p[4];
            }
            #pragma unroll
            for (int mt = 0; mt < 4; mt++)
                #pragma unroll
                for (int nt = 0; nt < 4; nt++)
                    mma8(c[mt][nt], af[mt], bf[nt]);
        }
        if (kt + 1 < DIM / 16) {
            const int nbuf = ((kt + 1) & 1) * 128 * SKA;
            #pragma unroll
            for (int l = 0; l < 2; l++) {
                int row = arow0 + l * 64;
                uint32_t* p = &As[nbuf + row * SKA + ac4];
                p[0] = f2tf(pa[l].x); p[1] = f2tf(pa[l].y); p[2] = f2tf(pa[l].z); p[3] = f2tf(pa[l].w);
                uint32_t* q = &Bs[nbuf + row * SKA + ac4];
                q[0] = f2tf(pw[l].x); q[1] = f2tf(pw[l].y); q[2] = f2tf(pw[l].z); q[3] = f2tf(pw[l].w);
            }
        }
    }

    // Epilogue
    #pragma unroll
    for (int mt = 0; mt < 4; mt++) {
        #pragma unroll
        for (int nt = 0; nt < 4; nt++) {
            const int n = n0 + wn + nt * 8 + 2 * t;
            const float2 bb = *(const float2*)&bias[n];
            #pragma unroll
            for (int rr = 0; rr < 2; rr++) {
                const int m = m0 + wm + mt * 16 + g + rr * 8;
                float2 v;
                v.x = (c[mt][nt][rr * 2 + 0] + bb.x) * scale;
                v.y = (c[mt][nt][rr * 2 + 1] + bb.y) * scale;
                if (scatter) {
                    int b = m >> 11, ts = m & 2047;
                    int h = n >> 6, d = n & 63;
                    *(float2*)&out[(size_t)(((b * NH + h) * QLEN) + ts) * DH + d] = v;
                } else {
                    *(float2*)&out[(size_t)m * DIM + n] = v;
                }
            }
        }
    }
}

// Fused QKV projection: grid.z selects {Q,K,V}
__global__ __launch_bounds__(256, 2) void gemm_qkv(
    const float* __restrict__ x,
    const float* __restrict__ wq, const float* __restrict__ bq,
    const float* __restrict__ wk, const float* __restrict__ bk,
    const float* __restrict__ wv, const float* __restrict__ bv,
    float* __restrict__ qp, float* __restrict__ kp, float* __restrict__ vp)
{
    __shared__ uint32_t As[2 * 128 * SKA];
    __shared__ uint32_t Bs[2 * 128 * SKA];
    const int z = blockIdx.z;
    const float* W = (z == 0) ? wq : (z == 1) ? wk : wv;
    const float* B = (z == 0) ? bq : (z == 1) ? bk : bv;
    float* out     = (z == 0) ? qp : (z == 1) ? kp : vp;
    const float scale = (z == 0) ? 0.125f : 1.0f;
    gemm_body(As, Bs, x, W, B, out, scale, 1);
}

__global__ __launch_bounds__(256, 2) void gemm_out(
    const float* __restrict__ A, const float* __restrict__ W,
    const float* __restrict__ bias, float* __restrict__ out)
{
    __shared__ uint32_t As[2 * 128 * SKA];
    __shared__ uint32_t Bs[2 * 128 * SKA];
    gemm_body(As, Bs, A, W, bias, out, 1.0f, 0);
}

// ---------------------------------------------------------------------------
// Flash attention v2, tf32 mma.sync.
// Block: 128 queries, 4 warps (warp = 32q x 64k), loop over 64-key tiles.
//  - QK B-fragments loaded with key permutation pi(c) = (c>>1)+4(c&1) so the
//    S accumulator registers ARE the PV A-fragments (no P smem round trip).
//  - Q staged once into fragment-ordered smem -> LDS.128 A-frag loads.
// Smem (u32 words): Qf 8192 (4w x 2mt x 8ks x 32lane x 4), Ks 64x68,
//                   Vs 64x72, mb 64.
// ---------------------------------------------------------------------------
#define SKK 68
#define SKV 72
#define AOFF_K  8192
#define AOFF_V  (AOFF_K + 64 * SKK)       // 12544
#define AOFF_MB (AOFF_V + 64 * SKV)       // 17152
#define ATTN_WORDS (AOFF_MB + 64)         // 17216
#define ATTN_SMEM_BYTES (ATTN_WORDS * 4)  // 68864

__global__ __launch_bounds__(128, 2) void attn_tf32(const int* __restrict__ mask)
{
    extern __shared__ uint32_t sm[];
    uint32_t* Qf = sm;
    uint32_t* Ks = sm + AOFF_K;
    uint32_t* Vs = sm + AOFF_V;
    float*    mb = (float*)(sm + AOFF_MB);

    const int bh = blockIdx.y, b = bh >> 4, h = bh & 15;
    const int q0 = blockIdx.x * 128;
    const int tid = threadIdx.x, lane = tid & 31, wid = tid >> 5;
    const int g = lane >> 2, t = lane & 3;
    const int qw = wid * 32;
    const int pg = (g >> 1) + ((g & 1) << 2);   // key permutation

    const float* Qg = g_q + (size_t)bh * QLEN * DH;
    const float* Kg = g_k + (size_t)bh * QLEN * DH;
    const float* Vg = g_v + (size_t)bh * QLEN * DH;

    // Stage Q tile (128x64) into fragment-ordered layout (once).
    // Qf word offset: (((w*2+mt)*8+ks)*32 + lane)*4 + j
    //   j0=(g,t) j1=(g+8,t) j2=(g,t+4) j3=(g+8,t+4)
    {
        const int row = tid;                 // one row per thread
        const int w  = row >> 5;
        const int mt = (row >> 4) & 1;
        const int rr = row & 15;
        const int gg = rr & 7;
        const int jr = rr >> 3;
        const float* qrow = &Qg[(size_t)(q0 + row) * DH];
        #pragma unroll
        for (int c4 = 0; c4 < 64; c4 += 4) {
            float4 v = *(const float4*)&qrow[c4];
            const int ks = c4 >> 3;
            const int j  = jr + ((c4 >> 1) & 2);   // +2 if (c4 % 8) == 4
            uint32_t* p = &Qf[((((w * 2 + mt) * 8 + ks) * 32) + gg * 4) * 4 + j];
            p[0]  = f2tf(v.x);
            p[4]  = f2tf(v.y);
            p[8]  = f2tf(v.z);
            p[12] = f2tf(v.w);
        }
    }

    float o[2][8][4] = {};
    float rm[2][2], rl[2][2];
    #pragma unroll
    for (int mt = 0; mt < 2; mt++)
        #pragma unroll
        for (int r = 0; r < 2; r++) { rm[mt][r] = -1e30f; rl[mt][r] = 0.0f; }

    #pragma unroll 1
    for (int kt = 0; kt < QLEN / 64; kt++) {
        const int kbase = kt * 64;
        __syncthreads();   // prior PV reads of Ks/Vs done (also covers Qf staging on kt=0)
        #pragma unroll
        for (int l = 0; l < 8; l++) {
            int idx = tid + l * 128;
            int row = idx >> 4, c4 = (idx & 15) * 4;
            float4 kv = *(const float4*)&Kg[(size_t)(kbase + row) * DH + c4];
            uint32_t* p = &Ks[row * SKK + c4];
            p[0] = f2tf(kv.x); p[1] = f2tf(kv.y); p[2] = f2tf(kv.z); p[3] = f2tf(kv.w);
            float4 vv = *(const float4*)&Vg[(size_t)(kbase + row) * DH + c4];
            uint32_t* q = &Vs[row * SKV + c4];
            q[0] = f2tf(vv.x); q[1] = f2tf(vv.y); q[2] = f2tf(vv.z); q[3] = f2tf(vv.w);
        }
        if (tid < 64)
            mb[tid] = (mask[b * QLEN + kbase + tid] == 0) ? -1e30f : 0.0f;
        __syncthreads();

        // S = Q @ K^T with permuted key columns: S col c (in 8-group) = key pi(c)
        float s[2][8][4] = {};
        #pragma unroll
        for (int ks = 0; ks < 8; ks++) {
            const int kb = ks * 8;
            uint4 a0 = *(const uint4*)&Qf[(((wid * 2 + 0) * 8 + ks) * 32 + lane) * 4];
            uint4 a1 = *(const uint4*)&Qf[(((wid * 2 + 1) * 8 + ks) * 32 + lane) * 4];
            const uint32_t af0[4] = {a0.x, a0.y, a0.z, a0.w};
            const uint32_t af1[4] = {a1.x, a1.y, a1.z, a1.w};
            #pragma unroll
            for (int nt = 0; nt < 8; nt++) {
                uint32_t bf[2];
                const uint32_t* p = &Ks[(nt * 8 + pg) * SKK + kb + t];
                bf[0] = p[0]; bf[1] = p[4];
                mma8(s[0][nt], af0, bf);
                mma8(s[1][nt], af1, bf);
            }
        }

        // mask add: thread's cols are keys {t, t+4} of each 8-group
        #pragma unroll
        for (int nt = 0; nt < 8; nt++) {
            float b0 = mb[nt * 8 + t];
            float b1 = mb[nt * 8 + t + 4];
            #pragma unroll
            for (int mt = 0; mt < 2; mt++) {
                s[mt][nt][0] += b0; s[mt][nt][1] += b1;
                s[mt][nt][2] += b0; s[mt][nt][3] += b1;
            }
        }

        // online softmax (row groups g, g+8)
        #pragma unroll
        for (int mt = 0; mt < 2; mt++) {
            #pragma unroll
            for (int r = 0; r < 2; r++) {
                float mx = -1e30f;
                #pragma unroll
                for (int nt = 0; nt < 8; nt++)
                    mx = fmaxf(mx, fmaxf(s[mt][nt][r * 2], s[mt][nt][r * 2 + 1]));
                mx = fmaxf(mx, __shfl_xor_sync(0xffffffffu, mx, 1));
                mx = fmaxf(mx, __shfl_xor_sync(0xffffffffu, mx, 2));
                float mnew  = fmaxf(rm[mt][r], mx);
                float alpha = __expf(rm[mt][r] - mnew);
                rm[mt][r] = mnew;
                float rs = 0.0f;
                #pragma unroll
                for (int nt = 0; nt < 8; nt++) {
                    float p0 = __expf(s[mt][nt][r * 2]     - mnew);
                    float p1 = __expf(s[mt][nt][r * 2 + 1] - mnew);
                    s[mt][nt][r * 2] = p0; s[mt][nt][r * 2 + 1] = p1;
                    rs += p0 + p1;
                }
                rs += __shfl_xor_sync(0xffffffffu, rs, 1);
                rs += __shfl_xor_sync(0xffffffffu, rs, 2);
                rl[mt][r] = rl[mt][r] * alpha + rs;
                #pragma unroll
                for (int nt = 0; nt < 8; nt++) {
                    o[mt][nt][r * 2]     *= alpha;
                    o[mt][nt][r * 2 + 1] *= alpha;
                }
            }
        }

        // O += P @ V : PV A-fragments come straight from s registers.
        // a-frag order: j0=P(g, kb+t)=s[..][ks][0], j1=P(g+8, kb+t)=s[..][ks][2],
        //               j2=P(g, kb+t+4)=s[..][ks][1], j3=P(g+8, kb+t+4)=s[..][ks][3]
        #pragma unroll
        for (int ks = 0; ks < 8; ks++) {
            const int kb = ks * 8;
            uint32_t af[2][4];
            #pragma unroll
            for (int mt = 0; mt < 2; mt++) {
                af[mt][0] = f2tf(s[mt][ks][0]);
                af[mt][1] = f2tf(s[mt][ks][2]);
                af[mt][2] = f2tf(s[mt][ks][1]);
                af[mt][3] = f2tf(s[mt][ks][3]);
            }
            #pragma unroll
            for (int nt = 0; nt < 8; nt++) {
                uint32_t bf[2];
                bf[0] = Vs[(kb + t) * SKV + nt * 8 + g];
                bf[1] = Vs[(kb + t + 4) * SKV + nt * 8 + g];
                mma8(o[0][nt], af[0], bf);
                mma8(o[1][nt], af[1], bf);
            }
        }
    }

    // Epilogue: ctx[b, t, h*64 + d]
    #pragma unroll
    for (int mt = 0; mt < 2; mt++) {
        #pragma unroll
        for (int r = 0; r < 2; r++) {
            float inv = 1.0f / rl[mt][r];
            int row = q0 + qw + mt * 16 + g + r * 8;
            #pragma unroll
            for (int nt = 0; nt < 8; nt++) {
                float2 v;
                v.x = o[mt][nt][r * 2]     * inv;
                v.y = o[mt][nt][r * 2 + 1] * inv;
                *(float2*)&g_ctx[(size_t)(b * QLEN + row) * DIM + h * DH + nt * 8 + 2 * t] = v;
            }
        }
    }
}

// ---------------------------------------------------------------------------
extern "C" void kernel_launch(void* const* d_in, const int* in_sizes, int n_in,
                              void* d_out, int out_size)
{
    const float* x    = (const float*)d_in[0];
    const int*   mask = (const int*)  d_in[1];
    const float* wq   = (const float*)d_in[2];
    const float* bq   = (const float*)d_in[3];
    const float* wk   = (const float*)d_in[4];
    const float* bk   = (const float*)d_in[5];
    const float* wv   = (const float*)d_in[6];
    const float* bv   = (const float*)d_in[7];
    const float* wo   = (const float*)d_in[8];
    const float* bo   = (const float*)d_in[9];
    float* out = (float*)d_out;

    float *qp, *kp, *vp, *cp;
    cudaGetSymbolAddress((void**)&qp, g_q);
    cudaGetSymbolAddress((void**)&kp, g_k);
    cudaGetSymbolAddress((void**)&vp, g_v);
    cudaGetSymbolAddress((void**)&cp, g_ctx);

    cudaFuncSetAttribute(attn_tf32,
                         cudaFuncAttributeMaxDynamicSharedMemorySize, ATTN_SMEM_BYTES);

    dim3 gq(DIM / 128, MTOT / 128, 3);
    gemm_qkv<<<gq, 256>>>(x, wq, bq, wk, bk, wv, bv, qp, kp, vp);

    dim3 ga(QLEN / 128, BSZ * NH);
    attn_tf32<<<ga, 128, ATTN_SMEM_BYTES>>>(mask);

    dim3 go(DIM / 128, MTOT / 128);
    gemm_out<<<go, 256>>>(cp, wo, bo, out);
}

// round 7
// speedup vs baseline: 1.7641x; 1.6134x over previous
#include <cuda_runtime.h>
#include <stdint.h>

#define BSZ  4
#define QLEN 2048
#define DIM  1024
#define NH   16
#define DH   64
#define MTOT (BSZ * QLEN)   // 8192

// Scratch (allocation-free rule: __device__ globals)
__device__ float g_q[BSZ * NH * QLEN * DH];
__device__ float g_k[BSZ * NH * QLEN * DH];
__device__ float g_v[BSZ * NH * QLEN * DH];
__device__ float g_ctx[MTOT * DIM];

__device__ __forceinline__ uint32_t smem_u32(const void* p) {
    uint32_t a;
    asm("{ .reg .u64 t; cvta.to.shared.u64 t, %1; cvt.u32.u64 %0, t; }"
        : "=r"(a) : "l"(p));
    return a;
}

// pack two f32 -> f16x2 (lo in low half; first cvt source lands in HIGH half)
__device__ __forceinline__ uint32_t h2(float lo, float hi) {
    uint32_t r;
    asm("cvt.rn.f16x2.f32 %0, %1, %2;" : "=r"(r) : "f"(hi), "f"(lo));
    return r;
}

// D = A(16x16,row) * B(16x8,col) + D, fp16 in, fp32 accum
__device__ __forceinline__ void mma16(float c[4], const uint32_t a[4], const uint32_t b[2]) {
    asm volatile(
        "mma.sync.aligned.m16n8k16.row.col.f32.f16.f16.f32 "
        "{%0,%1,%2,%3}, {%4,%5,%6,%7}, {%8,%9}, {%0,%1,%2,%3};\n"
        : "+f"(c[0]), "+f"(c[1]), "+f"(c[2]), "+f"(c[3])
        : "r"(a[0]), "r"(a[1]), "r"(a[2]), "r"(a[3]), "r"(b[0]), "r"(b[1]));
}

__device__ __forceinline__ void ldsm_x4(uint32_t r[4], uint32_t addr) {
    asm volatile("ldmatrix.sync.aligned.m8n8.x4.shared.b16 {%0,%1,%2,%3}, [%4];"
        : "=r"(r[0]), "=r"(r[1]), "=r"(r[2]), "=r"(r[3]) : "r"(addr));
}
__device__ __forceinline__ void ldsm_x2(uint32_t r[2], uint32_t addr) {
    asm volatile("ldmatrix.sync.aligned.m8n8.x2.shared.b16 {%0,%1}, [%2];"
        : "=r"(r[0]), "=r"(r[1]) : "r"(addr));
}
__device__ __forceinline__ void ldsm_x2t(uint32_t r[2], uint32_t addr) {
    asm volatile("ldmatrix.sync.aligned.m8n8.x2.trans.shared.b16 {%0,%1}, [%2];"
        : "=r"(r[0]), "=r"(r[1]) : "r"(addr));
}

// ---------------------------------------------------------------------------
// fp16 GEMM: C = A[MTOT,1024] @ W[1024,1024]^T (+ bias) (* scale)
// BM=BN=128, BK=32, 256 threads, 8 warps (2m x 4n), warp tile 64x32.
// smem rows: 16 fp16x2 words + 4 pad = 20 (80 B, 16B-aligned rows).
// ---------------------------------------------------------------------------
#define SKW 20

__device__ __forceinline__ void gemm_body(
    uint32_t* As, uint32_t* Bs,          // [2][128*SKW] each
    const float* __restrict__ A, const float* __restrict__ W,
    const float* __restrict__ bias, float* __restrict__ out,
    float scale, int scatter)
{
    const int m0 = blockIdx.y * 128, n0 = blockIdx.x * 128;
    const int tid = threadIdx.x, lane = tid & 31, wid = tid >> 5;
    const int wm = (wid >> 2) * 64, wn = (wid & 3) * 32;
    const int g = lane >> 2, t = lane & 3;
    const uint32_t asb = smem_u32(As), bsb = smem_u32(Bs);

    const int srow = tid >> 3;            // 0..31 (rows srow + 32l)
    const int sc4  = (tid & 7) * 4;       // float col 0..28

    float4 pa[4], pw[4];
    #pragma unroll
    for (int l = 0; l < 4; l++) {
        int r = srow + l * 32;
        pa[l] = *(const float4*)&A[(size_t)(m0 + r) * DIM + sc4];
        pw[l] = *(const float4*)&W[(size_t)(n0 + r) * DIM + sc4];
    }
    #pragma unroll
    for (int l = 0; l < 4; l++) {
        int r = srow + l * 32;
        uint2 ua; ua.x = h2(pa[l].x, pa[l].y); ua.y = h2(pa[l].z, pa[l].w);
        *(uint2*)&As[r * SKW + (sc4 >> 1)] = ua;
        uint2 uw; uw.x = h2(pw[l].x, pw[l].y); uw.y = h2(pw[l].z, pw[l].w);
        *(uint2*)&Bs[r * SKW + (sc4 >> 1)] = uw;
    }

    float c[4][4][4] = {};

    // ldmatrix lane addresses (word offsets within a buffer)
    const int arow = (lane & 15);                 // A x4 row within 16
    const int asel = (lane >> 4) * 4;             // A x4 k-half word
    const int brow = (lane & 7);                  // B x2 row within 8
    const int bsel = ((lane >> 3) & 1) * 4;       // B x2 k-half word

    #pragma unroll 1
    for (int kt = 0; kt < DIM / 32; kt++) {
        const int buf = (kt & 1) * 128 * SKW;
        __syncthreads();
        if (kt + 1 < DIM / 32) {
            const int k0 = (kt + 1) * 32;
            #pragma unroll
            for (int l = 0; l < 4; l++) {
                int r = srow + l * 32;
                pa[l] = *(const float4*)&A[(size_t)(m0 + r) * DIM + k0 + sc4];
                pw[l] = *(const float4*)&W[(size_t)(n0 + r) * DIM + k0 + sc4];
            }
        }
        #pragma unroll
        for (int ks = 0; ks < 2; ks++) {
            uint32_t af[4][4], bf[4][2];
            #pragma unroll
            for (int mt = 0; mt < 4; mt++)
                ldsm_x4(af[mt], asb + 4u * (buf + (wm + mt * 16 + arow) * SKW + ks * 8 + asel));
            #pragma unroll
            for (int nt = 0; nt < 4; nt++)
                ldsm_x2(bf[nt], bsb + 4u * (buf + (wn + nt * 8 + brow) * SKW + ks * 8 + bsel));
            #pragma unroll
            for (int mt = 0; mt < 4; mt++)
                #pragma unroll
                for (int nt = 0; nt < 4; nt++)
                    mma16(c[mt][nt], af[mt], bf[nt]);
        }
        if (kt + 1 < DIM / 32) {
            const int nbuf = ((kt + 1) & 1) * 128 * SKW;
            #pragma unroll
            for (int l = 0; l < 4; l++) {
                int r = srow + l * 32;
                uint2 ua; ua.x = h2(pa[l].x, pa[l].y); ua.y = h2(pa[l].z, pa[l].w);
                *(uint2*)&As[nbuf + r * SKW + (sc4 >> 1)] = ua;
                uint2 uw; uw.x = h2(pw[l].x, pw[l].y); uw.y = h2(pw[l].z, pw[l].w);
                *(uint2*)&Bs[nbuf + r * SKW + (sc4 >> 1)] = uw;
            }
        }
    }

    // Epilogue
    #pragma unroll
    for (int mt = 0; mt < 4; mt++) {
        #pragma unroll
        for (int nt = 0; nt < 4; nt++) {
            const int n = n0 + wn + nt * 8 + 2 * t;
            const float2 bb = *(const float2*)&bias[n];
            #pragma unroll
            for (int rr = 0; rr < 2; rr++) {
                const int m = m0 + wm + mt * 16 + g + rr * 8;
                float2 v;
                v.x = (c[mt][nt][rr * 2 + 0] + bb.x) * scale;
                v.y = (c[mt][nt][rr * 2 + 1] + bb.y) * scale;
                if (scatter) {
                    int b = m >> 11, ts = m & 2047;
                    int h = n >> 6, d = n & 63;
                    *(float2*)&out[(size_t)(((b * NH + h) * QLEN) + ts) * DH + d] = v;
                } else {
                    *(float2*)&out[(size_t)m * DIM + n] = v;
                }
            }
        }
    }
}

__global__ __launch_bounds__(256, 2) void gemm_qkv(
    const float* __restrict__ x,
    const float* __restrict__ wq, const float* __restrict__ bq,
    const float* __restrict__ wk, const float* __restrict__ bk,
    const float* __restrict__ wv, const float* __restrict__ bv,
    float* __restrict__ qp, float* __restrict__ kp, float* __restrict__ vp)
{
    __shared__ __align__(16) uint32_t As[2 * 128 * SKW];
    __shared__ __align__(16) uint32_t Bs[2 * 128 * SKW];
    const int z = blockIdx.z;
    const float* W = (z == 0) ? wq : (z == 1) ? wk : wv;
    const float* B = (z == 0) ? bq : (z == 1) ? bk : bv;
    float* out     = (z == 0) ? qp : (z == 1) ? kp : vp;
    const float scale = (z == 0) ? 0.125f : 1.0f;
    gemm_body(As, Bs, x, W, B, out, scale, 1);
}

__global__ __launch_bounds__(256, 2) void gemm_out(
    const float* __restrict__ A, const float* __restrict__ W,
    const float* __restrict__ bias, float* __restrict__ out)
{
    __shared__ __align__(16) uint32_t As[2 * 128 * SKW];
    __shared__ __align__(16) uint32_t Bs[2 * 128 * SKW];
    gemm_body(As, Bs, A, W, bias, out, 1.0f, 0);
}

// ---------------------------------------------------------------------------
// fp16 flash attention. Block: 128 queries, 4 warps (warp = 32q x 64k).
// Q fragments register-resident; K/V via ldmatrix (V with .trans, no P smem).
// smem rows: 32 fp16x2 words + 4 pad = 36 (144 B, 16B-aligned rows).
// ---------------------------------------------------------------------------
#define SKQ 36
#define QOFF  0
#define KOFF  (128 * SKQ)            // 4608
#define VOFF  (KOFF + 64 * SKQ)      // 6912
#define MBOFF (VOFF + 64 * SKQ)      // 9216
#define ATTN_WORDS (MBOFF + 64)      // 9280 -> 37120 B

__global__ __launch_bounds__(128, 2) void attn_h(const int* __restrict__ mask)
{
    __shared__ __align__(16) uint32_t sm[ATTN_WORDS];
    float* mb = (float*)(sm + MBOFF);
    const uint32_t sb = smem_u32(sm);

    const int bh = blockIdx.y, b = bh >> 4, h = bh & 15;
    const int q0 = blockIdx.x * 128;
    const int tid = threadIdx.x, lane = tid & 31, wid = tid >> 5;
    const int g = lane >> 2, t = lane & 3;
    const int qw = wid * 32;

    const float* Qg = g_q + (size_t)bh * QLEN * DH;
    const float* Kg = g_k + (size_t)bh * QLEN * DH;
    const float* Vg = g_v + (size_t)bh * QLEN * DH;

    // ldmatrix lane address components
    const int arow = (lane & 15);
    const int asel = (lane >> 4) * 4;
    const int brow = (lane & 7);
    const int bsel = ((lane >> 3) & 1) * 4;
    const int vrow = (lane & 7) + ((lane >> 3) & 1) * 8;

    // Stage Q (128x64) to smem fp16, then pull fragments to registers.
    #pragma unroll
    for (int l = 0; l < 16; l++) {
        int idx = tid + l * 128;
        int row = idx >> 4, c4 = (idx & 15) * 4;
        float4 v = *(const float4*)&Qg[(size_t)(q0 + row) * DH + c4];
        uint2 u; u.x = h2(v.x, v.y); u.y = h2(v.z, v.w);
        *(uint2*)&sm[QOFF + row * SKQ + (c4 >> 1)] = u;
    }
    __syncthreads();
    uint32_t qf[2][4][4];
    #pragma unroll
    for (int mt = 0; mt < 2; mt++)
        #pragma unroll
        for (int ks = 0; ks < 4; ks++)
            ldsm_x4(qf[mt][ks],
                    sb + 4u * (QOFF + (qw + mt * 16 + arow) * SKQ + ks * 8 + asel));

    float o[2][8][4] = {};
    float rm[2][2], rl[2][2];
    #pragma unroll
    for (int mt = 0; mt < 2; mt++)
        #pragma unroll
        for (int r = 0; r < 2; r++) { rm[mt][r] = -1e30f; rl[mt][r] = 0.0f; }

    #pragma unroll 1
    for (int kt = 0; kt < QLEN / 64; kt++) {
        const int kbase = kt * 64;
        __syncthreads();   // prior QK/PV reads of K/V done
        #pragma unroll
        for (int l = 0; l < 8; l++) {           // FIX: 64 rows x 16 quads = 8 iters
            int idx = tid + l * 128;
            int row = idx >> 4, c4 = (idx & 15) * 4;
            float4 kv = *(const float4*)&Kg[(size_t)(kbase + row) * DH + c4];
            uint2 ku; ku.x = h2(kv.x, kv.y); ku.y = h2(kv.z, kv.w);
            *(uint2*)&sm[KOFF + row * SKQ + (c4 >> 1)] = ku;
            float4 vv = *(const float4*)&Vg[(size_t)(kbase + row) * DH + c4];
            uint2 vu; vu.x = h2(vv.x, vv.y); vu.y = h2(vv.z, vv.w);
            *(uint2*)&sm[VOFF + row * SKQ + (c4 >> 1)] = vu;
        }
        if (tid < 64)
            mb[tid] = (mask[b * QLEN + kbase + tid] == 0) ? -1e30f : 0.0f;
        __syncthreads();

        // S = Q @ K^T  (warp: 32q x 64k, 4 k16 steps)
        float s[2][8][4] = {};
        #pragma unroll
        for (int ks = 0; ks < 4; ks++) {
            #pragma unroll
            for (int nt = 0; nt < 8; nt++) {
                uint32_t bf[2];
                ldsm_x2(bf, sb + 4u * (KOFF + (nt * 8 + brow) * SKQ + ks * 8 + bsel));
                mma16(s[0][nt], qf[0][ks], bf);
                mma16(s[1][nt], qf[1][ks], bf);
            }
        }

        // mask add (thread owns cols 2t, 2t+1 of each 8-key group)
        #pragma unroll
        for (int nt = 0; nt < 8; nt++) {
            float b0 = mb[nt * 8 + 2 * t];
            float b1 = mb[nt * 8 + 2 * t + 1];
            #pragma unroll
            for (int mt = 0; mt < 2; mt++) {
                s[mt][nt][0] += b0; s[mt][nt][1] += b1;
                s[mt][nt][2] += b0; s[mt][nt][3] += b1;
            }
        }

        // online softmax (row groups g, g+8; reduce over 4 t-lanes)
        #pragma unroll
        for (int mt = 0; mt < 2; mt++) {
            #pragma unroll
            for (int r = 0; r < 2; r++) {
                float mx = -1e30f;
                #pragma unroll
                for (int nt = 0; nt < 8; nt++)
                    mx = fmaxf(mx, fmaxf(s[mt][nt][r * 2], s[mt][nt][r * 2 + 1]));
                mx = fmaxf(mx, __shfl_xor_sync(0xffffffffu, mx, 1));
                mx = fmaxf(mx, __shfl_xor_sync(0xffffffffu, mx, 2));
                float mnew  = fmaxf(rm[mt][r], mx);
                float alpha = __expf(rm[mt][r] - mnew);
                rm[mt][r] = mnew;
                float rs = 0.0f;
                #pragma unroll
                for (int nt = 0; nt < 8; nt++) {
                    float p0 = __expf(s[mt][nt][r * 2]     - mnew);
                    float p1 = __expf(s[mt][nt][r * 2 + 1] - mnew);
                    s[mt][nt][r * 2] = p0; s[mt][nt][r * 2 + 1] = p1;
                    rs += p0 + p1;
                }
                rs += __shfl_xor_sync(0xffffffffu, rs, 1);
                rs += __shfl_xor_sync(0xffffffffu, rs, 2);
                rl[mt][r] = rl[mt][r] * alpha + rs;
                #pragma unroll
                for (int nt = 0; nt < 8; nt++) {
                    o[mt][nt][r * 2]     *= alpha;
                    o[mt][nt][r * 2 + 1] *= alpha;
                }
            }
        }

        // O += P @ V : A-fragments packed straight from s; V via ldmatrix.trans
        #pragma unroll
        for (int ks = 0; ks < 4; ks++) {
            uint32_t af[2][4];
            #pragma unroll
            for (int mt = 0; mt < 2; mt++) {
                af[mt][0] = h2(s[mt][2 * ks][0],     s[mt][2 * ks][1]);
                af[mt][1] = h2(s[mt][2 * ks][2],     s[mt][2 * ks][3]);
                af[mt][2] = h2(s[mt][2 * ks + 1][0], s[mt][2 * ks + 1][1]);
                af[mt][3] = h2(s[mt][2 * ks + 1][2], s[mt][2 * ks + 1][3]);
            }
            #pragma unroll
            for (int nt = 0; nt < 8; nt++) {
                uint32_t bf[2];
                ldsm_x2t(bf, sb + 4u * (VOFF + (16 * ks + vrow) * SKQ + nt * 4));
                mma16(o[0][nt], af[0], bf);
                mma16(o[1][nt], af[1], bf);
            }
        }
    }

    // Epilogue: ctx[b, t, h*64 + d]
    #pragma unroll
    for (int mt = 0; mt < 2; mt++) {
        #pragma unroll
        for (int r = 0; r < 2; r++) {
            float inv = 1.0f / rl[mt][r];
            int row = q0 + qw + mt * 16 + g + r * 8;
            #pragma unroll
            for (int nt = 0; nt < 8; nt++) {
                float2 v;
                v.x = o[mt][nt][r * 2]     * inv;
                v.y = o[mt][nt][r * 2 + 1] * inv;
                *(float2*)&g_ctx[(size_t)(b * QLEN + row) * DIM + h * DH + nt * 8 + 2 * t] = v;
            }
        }
    }
}

// ---------------------------------------------------------------------------
extern "C" void kernel_launch(void* const* d_in, const int* in_sizes, int n_in,
                              void* d_out, int out_size)
{
    const float* x    = (const float*)d_in[0];
    const int*   mask = (const int*)  d_in[1];
    const float* wq   = (const float*)d_in[2];
    const float* bq   = (const float*)d_in[3];
    const float* wk   = (const float*)d_in[4];
    const float* bk   = (const float*)d_in[5];
    const float* wv   = (const float*)d_in[6];
    const float* bv   = (const float*)d_in[7];
    const float* wo   = (const float*)d_in[8];
    const float* bo   = (const float*)d_in[9];
    float* out = (float*)d_out;

    float *qp, *kp, *vp, *cp;
    cudaGetSymbolAddress((void**)&qp, g_q);
    cudaGetSymbolAddress((void**)&kp, g_k);
    cudaGetSymbolAddress((void**)&vp, g_v);
    cudaGetSymbolAddress((void**)&cp, g_ctx);

    dim3 gq(DIM / 128, MTOT / 128, 3);
    gemm_qkv<<<gq, 256>>>(x, wq, bq, wk, bk, wv, bv, qp, kp, vp);

    dim3 ga(QLEN / 128, BSZ * NH);
    attn_h<<<ga, 128>>>(mask);

    dim3 go(DIM / 128, MTOT / 128);
    gemm_out<<<go, 256>>>(cp, wo, bo, out);
}

// round 8
// speedup vs baseline: 2.1914x; 1.2422x over previous
#include <cuda_runtime.h>
#include <cuda_fp16.h>
#include <stdint.h>

#define BSZ  4
#define QLEN 2048
#define DIM  1024
#define NH   16
#define DH   64
#define MTOT (BSZ * QLEN)   // 8192

// Scratch (allocation-free rule: __device__ globals) — fp16 dataflow
__device__ __half g_xh [MTOT * DIM];
__device__ __half g_wh [4][DIM * DIM];          // wq, wk, wv, wo
__device__ __half g_qh [BSZ * NH * QLEN * DH];
__device__ __half g_kh [BSZ * NH * QLEN * DH];
__device__ __half g_vh [BSZ * NH * QLEN * DH];
__device__ __half g_ctxh[MTOT * DIM];

__device__ __forceinline__ uint32_t smem_u32(const void* p) {
    uint32_t a;
    asm("{ .reg .u64 t; cvta.to.shared.u64 t, %1; cvt.u32.u64 %0, t; }"
        : "=r"(a) : "l"(p));
    return a;
}

// pack two f32 -> f16x2 (lo in low half)
__device__ __forceinline__ uint32_t h2(float lo, float hi) {
    uint32_t r;
    asm("cvt.rn.f16x2.f32 %0, %1, %2;" : "=r"(r) : "f"(hi), "f"(lo));
    return r;
}

__device__ __forceinline__ void mma16(float c[4], const uint32_t a[4], const uint32_t b[2]) {
    asm volatile(
        "mma.sync.aligned.m16n8k16.row.col.f32.f16.f16.f32 "
        "{%0,%1,%2,%3}, {%4,%5,%6,%7}, {%8,%9}, {%0,%1,%2,%3};\n"
        : "+f"(c[0]), "+f"(c[1]), "+f"(c[2]), "+f"(c[3])
        : "r"(a[0]), "r"(a[1]), "r"(a[2]), "r"(a[3]), "r"(b[0]), "r"(b[1]));
}

__device__ __forceinline__ void ldsm_x4(uint32_t r[4], uint32_t addr) {
    asm volatile("ldmatrix.sync.aligned.m8n8.x4.shared.b16 {%0,%1,%2,%3}, [%4];"
        : "=r"(r[0]), "=r"(r[1]), "=r"(r[2]), "=r"(r[3]) : "r"(addr));
}
__device__ __forceinline__ void ldsm_x2(uint32_t r[2], uint32_t addr) {
    asm volatile("ldmatrix.sync.aligned.m8n8.x2.shared.b16 {%0,%1}, [%2];"
        : "=r"(r[0]), "=r"(r[1]) : "r"(addr));
}
__device__ __forceinline__ void ldsm_x2t(uint32_t r[2], uint32_t addr) {
    asm volatile("ldmatrix.sync.aligned.m8n8.x2.trans.shared.b16 {%0,%1}, [%2];"
        : "=r"(r[0]), "=r"(r[1]) : "r"(addr));
}

__device__ __forceinline__ void cp16(uint32_t dst, const void* src) {
    asm volatile("cp.async.ca.shared.global [%0], [%1], 16;\n" :: "r"(dst), "l"(src));
}
#define CP_COMMIT() asm volatile("cp.async.commit_group;\n" ::: "memory")
#define CP_WAIT(n)  asm volatile("cp.async.wait_group %0;\n" :: "n"(n) : "memory")

// ---------------------------------------------------------------------------
// f32 -> f16 convert (vectorized, 8 elems/thread)
// ---------------------------------------------------------------------------
__global__ __launch_bounds__(256) void f2h_kernel(
    const float* __restrict__ src, __half* __restrict__ dst)
{
    int i = (blockIdx.x * 256 + threadIdx.x) * 8;
    float4 a = *(const float4*)&src[i];
    float4 b = *(const float4*)&src[i + 4];
    uint4 u;
    u.x = h2(a.x, a.y); u.y = h2(a.z, a.w);
    u.z = h2(b.x, b.y); u.w = h2(b.z, b.w);
    *(uint4*)&dst[i] = u;
}

// 4 weight matrices in one launch (grid.y selects)
__global__ __launch_bounds__(256) void f2h_w_kernel(
    const float* __restrict__ w0, const float* __restrict__ w1,
    const float* __restrict__ w2, const float* __restrict__ w3)
{
    const float* src = (blockIdx.y == 0) ? w0 : (blockIdx.y == 1) ? w1
                     : (blockIdx.y == 2) ? w2 : w3;
    __half* dst = g_wh[blockIdx.y];
    int i = (blockIdx.x * 256 + threadIdx.x) * 8;
    float4 a = *(const float4*)&src[i];
    float4 b = *(const float4*)&src[i + 4];
    uint4 u;
    u.x = h2(a.x, a.y); u.y = h2(a.z, a.w);
    u.z = h2(b.x, b.y); u.w = h2(b.z, b.w);
    *(uint4*)&dst[i] = u;
}

// ---------------------------------------------------------------------------
// fp16 GEMM with cp.async: C = A[MTOT,1024] @ W[1024,1024]^T (+ bias)(*scale)
// BM=BN=128, BK=64, 256 threads, 8 warps (2m x 4n), warp tile 64x32.
// smem rows: 64 halves + 8 pad = 36 words (144 B). Double buffered.
// ---------------------------------------------------------------------------
#define SKW 36
#define TILE_W (128 * SKW)                 // 4608 words per matrix-buffer
#define GEMM_WORDS (4 * TILE_W)            // A0 A1 B0 B1
#define GEMM_SMEM_BYTES (GEMM_WORDS * 4)   // 73728

__device__ __forceinline__ void gemm_issue(
    uint32_t sb, int bufA, int bufB,
    const __half* __restrict__ A, const __half* __restrict__ W,
    int m0, int n0, int k0, int tid)
{
    #pragma unroll
    for (int l = 0; l < 4; l++) {
        int cc = tid + l * 256;            // 0..1023
        int row = cc >> 3, ch = (cc & 7) * 8;   // halves
        uint32_t da = sb + 4u * (bufA + row * SKW + (ch >> 1));
        cp16(da, A + (size_t)(m0 + row) * DIM + k0 + ch);
        uint32_t db = sb + 4u * (bufB + row * SKW + (ch >> 1));
        cp16(db, W + (size_t)(n0 + row) * DIM + k0 + ch);
    }
}

template <int OUT_HALF>
__device__ __forceinline__ void gemm_body_h(
    const __half* __restrict__ A, const __half* __restrict__ W,
    const float* __restrict__ bias, void* __restrict__ out,
    float scale, int scatter)
{
    extern __shared__ uint32_t sm[];
    const uint32_t sb = smem_u32(sm);
    const int m0 = blockIdx.y * 128, n0 = blockIdx.x * 128;
    const int tid = threadIdx.x, lane = tid & 31, wid = tid >> 5;
    const int wm = (wid >> 2) * 64, wn = (wid & 3) * 32;
    const int g = lane >> 2, t = lane & 3;

    const int arow = (lane & 15);
    const int asel = (lane >> 4) * 4;
    const int brow = (lane & 7);
    const int bsel = ((lane >> 3) & 1) * 4;

    float c[4][4][4] = {};

    gemm_issue(sb, 0, 2 * TILE_W, A, W, m0, n0, 0, tid);
    CP_COMMIT();

    const int NT = DIM / 64;   // 16
    #pragma unroll 1
    for (int kt = 0; kt < NT; kt++) {
        const int buf = kt & 1;
        if (kt + 1 < NT) {
            gemm_issue(sb, (kt + 1 & 1) * TILE_W, (2 + (kt + 1 & 1)) * TILE_W,
                       A, W, m0, n0, (kt + 1) * 64, tid);
            CP_COMMIT();
            CP_WAIT(1);
        } else {
            CP_WAIT(0);
        }
        __syncthreads();

        const int ab = buf * TILE_W, bb = (2 + buf) * TILE_W;
        #pragma unroll
        for (int ks = 0; ks < 4; ks++) {
            uint32_t af[4][4], bf[4][2];
            #pragma unroll
            for (int mt = 0; mt < 4; mt++)
                ldsm_x4(af[mt], sb + 4u * (ab + (wm + mt * 16 + arow) * SKW + ks * 8 + asel));
            #pragma unroll
            for (int nt = 0; nt < 4; nt++)
                ldsm_x2(bf[nt], sb + 4u * (bb + (wn + nt * 8 + brow) * SKW + ks * 8 + bsel));
            #pragma unroll
            for (int mt = 0; mt < 4; mt++)
                #pragma unroll
                for (int nt = 0; nt < 4; nt++)
                    mma16(c[mt][nt], af[mt], bf[nt]);
        }
        __syncthreads();   // all reads of buf done before kt+1 issues into it
    }

    // Epilogue
    #pragma unroll
    for (int mt = 0; mt < 4; mt++) {
        #pragma unroll
        for (int nt = 0; nt < 4; nt++) {
            const int n = n0 + wn + nt * 8 + 2 * t;
            const float2 bb2 = *(const float2*)&bias[n];
            #pragma unroll
            for (int rr = 0; rr < 2; rr++) {
                const int m = m0 + wm + mt * 16 + g + rr * 8;
                float vx = (c[mt][nt][rr * 2 + 0] + bb2.x) * scale;
                float vy = (c[mt][nt][rr * 2 + 1] + bb2.y) * scale;
                if (OUT_HALF) {
                    uint32_t pv = h2(vx, vy);
                    size_t off;
                    if (scatter) {
                        int b = m >> 11, ts = m & 2047;
                        int h = n >> 6, d = n & 63;
                        off = (size_t)(((b * NH + h) * QLEN) + ts) * DH + d;
                    } else {
                        off = (size_t)m * DIM + n;
                    }
                    *(uint32_t*)((__half*)out + off) = pv;
                } else {
                    float2 v; v.x = vx; v.y = vy;
                    *(float2*)((float*)out + (size_t)m * DIM + n) = v;
                }
            }
        }
    }
}

__global__ __launch_bounds__(256, 2) void gemm_qkv(
    const float* __restrict__ bq, const float* __restrict__ bk,
    const float* __restrict__ bv)
{
    const int z = blockIdx.z;
    const __half* W   = g_wh[z];
    const float* B    = (z == 0) ? bq : (z == 1) ? bk : bv;
    __half* out       = (z == 0) ? g_qh : (z == 1) ? g_kh : g_vh;
    const float scale = (z == 0) ? 0.125f : 1.0f;
    gemm_body_h<1>(g_xh, W, B, out, scale, 1);
}

__global__ __launch_bounds__(256, 2) void gemm_out(
    const float* __restrict__ bo, float* __restrict__ out)
{
    gemm_body_h<0>(g_ctxh, g_wh[3], bo, out, 1.0f, 0);
}

// ---------------------------------------------------------------------------
// fp16 flash attention. Block: 128 queries, 4 warps (warp = 32q x 64k).
// Q fragments register-resident; K/V uint4 staged, ldmatrix (V .trans).
// smem rows: 64 halves + 8 pad = 36 words.
// ---------------------------------------------------------------------------
#define SKQ 36
#define QOFF  0
#define KOFF  (128 * SKQ)            // 4608
#define VOFF  (KOFF + 64 * SKQ)      // 6912
#define MBOFF (VOFF + 64 * SKQ)      // 9216
#define ATTN_WORDS (MBOFF + 64)      // 9280 -> 37120 B

__global__ __launch_bounds__(128, 2) void attn_h(const int* __restrict__ mask)
{
    __shared__ __align__(16) uint32_t sm[ATTN_WORDS];
    float* mb = (float*)(sm + MBOFF);
    const uint32_t sb = smem_u32(sm);

    const int bh = blockIdx.y, b = bh >> 4, h = bh & 15;
    const int q0 = blockIdx.x * 128;
    const int tid = threadIdx.x, lane = tid & 31, wid = tid >> 5;
    const int g = lane >> 2, t = lane & 3;
    const int qw = wid * 32;

    const __half* Qg = g_qh + (size_t)bh * QLEN * DH;
    const __half* Kg = g_kh + (size_t)bh * QLEN * DH;
    const __half* Vg = g_vh + (size_t)bh * QLEN * DH;

    const int arow = (lane & 15);
    const int asel = (lane >> 4) * 4;
    const int brow = (lane & 7);
    const int bsel = ((lane >> 3) & 1) * 4;
    const int vrow = (lane & 7) + ((lane >> 3) & 1) * 8;

    // Stage Q (128x64 halves), pull fragments to registers.
    #pragma unroll
    for (int l = 0; l < 8; l++) {
        int idx = tid + l * 128;            // 0..1023
        int row = idx >> 3, ch = (idx & 7) * 8;
        *(uint4*)&sm[QOFF + row * SKQ + (ch >> 1)] =
            *(const uint4*)&Qg[(size_t)(q0 + row) * DH + ch];
    }
    __syncthreads();
    uint32_t qf[2][4][4];
    #pragma unroll
    for (int mt = 0; mt < 2; mt++)
        #pragma unroll
        for (int ks = 0; ks < 4; ks++)
            ldsm_x4(qf[mt][ks],
                    sb + 4u * (QOFF + (qw + mt * 16 + arow) * SKQ + ks * 8 + asel));

    float o[2][8][4] = {};
    float rm[2][2], rl[2][2];
    #pragma unroll
    for (int mt = 0; mt < 2; mt++)
        #pragma unroll
        for (int r = 0; r < 2; r++) { rm[mt][r] = -1e30f; rl[mt][r] = 0.0f; }

    #pragma unroll 1
    for (int kt = 0; kt < QLEN / 64; kt++) {
        const int kbase = kt * 64;
        __syncthreads();
        #pragma unroll
        for (int l = 0; l < 4; l++) {
            int idx = tid + l * 128;        // 0..511
            int row = idx >> 3, ch = (idx & 7) * 8;
            *(uint4*)&sm[KOFF + row * SKQ + (ch >> 1)] =
                *(const uint4*)&Kg[(size_t)(kbase + row) * DH + ch];
            *(uint4*)&sm[VOFF + row * SKQ + (ch >> 1)] =
                *(const uint4*)&Vg[(size_t)(kbase + row) * DH + ch];
        }
        if (tid < 64)
            mb[tid] = (mask[b * QLEN + kbase + tid] == 0) ? -1e30f : 0.0f;
        __syncthreads();

        // S = Q @ K^T
        float s[2][8][4] = {};
        #pragma unroll
        for (int ks = 0; ks < 4; ks++) {
            #pragma unroll
            for (int nt = 0; nt < 8; nt++) {
                uint32_t bf[2];
                ldsm_x2(bf, sb + 4u * (KOFF + (nt * 8 + brow) * SKQ + ks * 8 + bsel));
                mma16(s[0][nt], qf[0][ks], bf);
                mma16(s[1][nt], qf[1][ks], bf);
            }
        }

        // mask add
        #pragma unroll
        for (int nt = 0; nt < 8; nt++) {
            float b0 = mb[nt * 8 + 2 * t];
            float b1 = mb[nt * 8 + 2 * t + 1];
            #pragma unroll
            for (int mt = 0; mt < 2; mt++) {
                s[mt][nt][0] += b0; s[mt][nt][1] += b1;
                s[mt][nt][2] += b0; s[mt][nt][3] += b1;
            }
        }

        // online softmax
        #pragma unroll
        for (int mt = 0; mt < 2; mt++) {
            #pragma unroll
            for (int r = 0; r < 2; r++) {
                float mx = -1e30f;
                #pragma unroll
                for (int nt = 0; nt < 8; nt++)
                    mx = fmaxf(mx, fmaxf(s[mt][nt][r * 2], s[mt][nt][r * 2 + 1]));
                mx = fmaxf(mx, __shfl_xor_sync(0xffffffffu, mx, 1));
                mx = fmaxf(mx, __shfl_xor_sync(0xffffffffu, mx, 2));
                float mnew  = fmaxf(rm[mt][r], mx);
                float alpha = __expf(rm[mt][r] - mnew);
                rm[mt][r] = mnew;
                float rs = 0.0f;
                #pragma unroll
                for (int nt = 0; nt < 8; nt++) {
                    float p0 = __expf(s[mt][nt][r * 2]     - mnew);
                    float p1 = __expf(s[mt][nt][r * 2 + 1] - mnew);
                    s[mt][nt][r * 2] = p0; s[mt][nt][r * 2 + 1] = p1;
                    rs += p0 + p1;
                }
                rs += __shfl_xor_sync(0xffffffffu, rs, 1);
                rs += __shfl_xor_sync(0xffffffffu, rs, 2);
                rl[mt][r] = rl[mt][r] * alpha + rs;
                #pragma unroll
                for (int nt = 0; nt < 8; nt++) {
                    o[mt][nt][r * 2]     *= alpha;
                    o[mt][nt][r * 2 + 1] *= alpha;
                }
            }
        }

        // O += P @ V
        #pragma unroll
        for (int ks = 0; ks < 4; ks++) {
            uint32_t af[2][4];
            #pragma unroll
            for (int mt = 0; mt < 2; mt++) {
                af[mt][0] = h2(s[mt][2 * ks][0],     s[mt][2 * ks][1]);
                af[mt][1] = h2(s[mt][2 * ks][2],     s[mt][2 * ks][3]);
                af[mt][2] = h2(s[mt][2 * ks + 1][0], s[mt][2 * ks + 1][1]);
                af[mt][3] = h2(s[mt][2 * ks + 1][2], s[mt][2 * ks + 1][3]);
            }
            #pragma unroll
            for (int nt = 0; nt < 8; nt++) {
                uint32_t bf[2];
                ldsm_x2t(bf, sb + 4u * (VOFF + (16 * ks + vrow) * SKQ + nt * 4));
                mma16(o[0][nt], af[0], bf);
                mma16(o[1][nt], af[1], bf);
            }
        }
    }

    // Epilogue: ctx fp16 [b, t, h*64 + d]
    #pragma unroll
    for (int mt = 0; mt < 2; mt++) {
        #pragma unroll
        for (int r = 0; r < 2; r++) {
            float inv = 1.0f / rl[mt][r];
            int row = q0 + qw + mt * 16 + g + r * 8;
            #pragma unroll
            for (int nt = 0; nt < 8; nt++) {
                uint32_t pv = h2(o[mt][nt][r * 2] * inv, o[mt][nt][r * 2 + 1] * inv);
                *(uint32_t*)&g_ctxh[(size_t)(b * QLEN + row) * DIM + h * DH + nt * 8 + 2 * t] = pv;
            }
        }
    }
}

// ---------------------------------------------------------------------------
extern "C" void kernel_launch(void* const* d_in, const int* in_sizes, int n_in,
                              void* d_out, int out_size)
{
    const float* x    = (const float*)d_in[0];
    const int*   mask = (const int*)  d_in[1];
    const float* wq   = (const float*)d_in[2];
    const float* bq   = (const float*)d_in[3];
    const float* wk   = (const float*)d_in[4];
    const float* bk   = (const float*)d_in[5];
    const float* wv   = (const float*)d_in[6];
    const float* bv   = (const float*)d_in[7];
    const float* wo   = (const float*)d_in[8];
    const float* bo   = (const float*)d_in[9];
    float* out = (float*)d_out;

    __half* xh;
    cudaGetSymbolAddress((void**)&xh, g_xh);

    cudaFuncSetAttribute(gemm_qkv,
                         cudaFuncAttributeMaxDynamicSharedMemorySize, GEMM_SMEM_BYTES);
    cudaFuncSetAttribute(gemm_out,
                         cudaFuncAttributeMaxDynamicSharedMemorySize, GEMM_SMEM_BYTES);

    // fp32 -> fp16 converts
    f2h_kernel<<<MTOT * DIM / 2048, 256>>>(x, xh);
    dim3 gw(DIM * DIM / 2048, 4);
    f2h_w_kernel<<<gw, 256>>>(wq, wk, wv, wo);

    // QKV projections
    dim3 gq(DIM / 128, MTOT / 128, 3);
    gemm_qkv<<<gq, 256, GEMM_SMEM_BYTES>>>(bq, bk, bv);

    // Attention
    dim3 ga(QLEN / 128, BSZ * NH);
    attn_h<<<ga, 128>>>(mask);

    // Output projection
    dim3 go(DIM / 128, MTOT / 128);
    gemm_out<<<go, 256, GEMM_SMEM_BYTES>>>(bo, out);
}

// round 9
// speedup vs baseline: 2.2350x; 1.0199x over previous
#include <cuda_runtime.h>
#include <cuda_fp16.h>
#include <stdint.h>

#define BSZ  4
#define QLEN 2048
#define DIM  1024
#define NH   16
#define DH   64
#define MTOT (BSZ * QLEN)   // 8192

// Scratch (allocation-free rule: __device__ globals) — fp16 dataflow
__device__ __half g_xh [MTOT * DIM];
__device__ __half g_wh [4][DIM * DIM];          // wq, wk, wv, wo
__device__ __half g_qh [BSZ * NH * QLEN * DH];
__device__ __half g_kh [BSZ * NH * QLEN * DH];
__device__ __half g_vh [BSZ * NH * QLEN * DH];
__device__ __half g_ctxh[MTOT * DIM];

__device__ __forceinline__ uint32_t smem_u32(const void* p) {
    uint32_t a;
    asm("{ .reg .u64 t; cvta.to.shared.u64 t, %1; cvt.u32.u64 %0, t; }"
        : "=r"(a) : "l"(p));
    return a;
}

// pack two f32 -> f16x2 (lo in low half)
__device__ __forceinline__ uint32_t h2(float lo, float hi) {
    uint32_t r;
    asm("cvt.rn.f16x2.f32 %0, %1, %2;" : "=r"(r) : "f"(hi), "f"(lo));
    return r;
}

// 2-wide exp2 in fp16 (one MUFU op for two values)
__device__ __forceinline__ uint32_t ex2_h2(uint32_t x) {
    uint32_t r;
    asm("ex2.approx.f16x2 %0, %1;" : "=r"(r) : "r"(x));
    return r;
}

__device__ __forceinline__ void mma16(float c[4], const uint32_t a[4], const uint32_t b[2]) {
    asm volatile(
        "mma.sync.aligned.m16n8k16.row.col.f32.f16.f16.f32 "
        "{%0,%1,%2,%3}, {%4,%5,%6,%7}, {%8,%9}, {%0,%1,%2,%3};\n"
        : "+f"(c[0]), "+f"(c[1]), "+f"(c[2]), "+f"(c[3])
        : "r"(a[0]), "r"(a[1]), "r"(a[2]), "r"(a[3]), "r"(b[0]), "r"(b[1]));
}

__device__ __forceinline__ void ldsm_x4(uint32_t r[4], uint32_t addr) {
    asm volatile("ldmatrix.sync.aligned.m8n8.x4.shared.b16 {%0,%1,%2,%3}, [%4];"
        : "=r"(r[0]), "=r"(r[1]), "=r"(r[2]), "=r"(r[3]) : "r"(addr));
}
__device__ __forceinline__ void ldsm_x2(uint32_t r[2], uint32_t addr) {
    asm volatile("ldmatrix.sync.aligned.m8n8.x2.shared.b16 {%0,%1}, [%2];"
        : "=r"(r[0]), "=r"(r[1]) : "r"(addr));
}
__device__ __forceinline__ void ldsm_x2t(uint32_t r[2], uint32_t addr) {
    asm volatile("ldmatrix.sync.aligned.m8n8.x2.trans.shared.b16 {%0,%1}, [%2];"
        : "=r"(r[0]), "=r"(r[1]) : "r"(addr));
}

__device__ __forceinline__ void cp16(uint32_t dst, const void* src) {
    asm volatile("cp.async.ca.shared.global [%0], [%1], 16;\n" :: "r"(dst), "l"(src));
}
#define CP_COMMIT() asm volatile("cp.async.commit_group;\n" ::: "memory")
#define CP_WAIT(n)  asm volatile("cp.async.wait_group %0;\n" :: "n"(n) : "memory")

// ---------------------------------------------------------------------------
// f32 -> f16 convert (vectorized, 8 elems/thread)
// ---------------------------------------------------------------------------
__global__ __launch_bounds__(256) void f2h_kernel(
    const float* __restrict__ src, __half* __restrict__ dst)
{
    int i = (blockIdx.x * 256 + threadIdx.x) * 8;
    float4 a = *(const float4*)&src[i];
    float4 b = *(const float4*)&src[i + 4];
    uint4 u;
    u.x = h2(a.x, a.y); u.y = h2(a.z, a.w);
    u.z = h2(b.x, b.y); u.w = h2(b.z, b.w);
    *(uint4*)&dst[i] = u;
}

__global__ __launch_bounds__(256) void f2h_w_kernel(
    const float* __restrict__ w0, const float* __restrict__ w1,
    const float* __restrict__ w2, const float* __restrict__ w3)
{
    const float* src = (blockIdx.y == 0) ? w0 : (blockIdx.y == 1) ? w1
                     : (blockIdx.y == 2) ? w2 : w3;
    __half* dst = g_wh[blockIdx.y];
    int i = (blockIdx.x * 256 + threadIdx.x) * 8;
    float4 a = *(const float4*)&src[i];
    float4 b = *(const float4*)&src[i + 4];
    uint4 u;
    u.x = h2(a.x, a.y); u.y = h2(a.z, a.w);
    u.z = h2(b.x, b.y); u.w = h2(b.z, b.w);
    *(uint4*)&dst[i] = u;
}

// ---------------------------------------------------------------------------
// fp16 GEMM with cp.async: C = A[MTOT,1024] @ W[1024,1024]^T (+ bias)(*scale)
// BM=BN=128, BK=64, 256 threads, 8 warps (2m x 4n), warp tile 64x32.
// ---------------------------------------------------------------------------
#define SKW 36
#define TILE_W (128 * SKW)
#define GEMM_WORDS (4 * TILE_W)
#define GEMM_SMEM_BYTES (GEMM_WORDS * 4)   // 73728

__device__ __forceinline__ void gemm_issue(
    uint32_t sb, int bufA, int bufB,
    const __half* __restrict__ A, const __half* __restrict__ W,
    int m0, int n0, int k0, int tid)
{
    #pragma unroll
    for (int l = 0; l < 4; l++) {
        int cc = tid + l * 256;
        int row = cc >> 3, ch = (cc & 7) * 8;
        uint32_t da = sb + 4u * (bufA + row * SKW + (ch >> 1));
        cp16(da, A + (size_t)(m0 + row) * DIM + k0 + ch);
        uint32_t db = sb + 4u * (bufB + row * SKW + (ch >> 1));
        cp16(db, W + (size_t)(n0 + row) * DIM + k0 + ch);
    }
}

template <int OUT_HALF>
__device__ __forceinline__ void gemm_body_h(
    const __half* __restrict__ A, const __half* __restrict__ W,
    const float* __restrict__ bias, void* __restrict__ out,
    float scale, int scatter)
{
    extern __shared__ uint32_t sm[];
    const uint32_t sb = smem_u32(sm);
    const int m0 = blockIdx.y * 128, n0 = blockIdx.x * 128;
    const int tid = threadIdx.x, lane = tid & 31, wid = tid >> 5;
    const int wm = (wid >> 2) * 64, wn = (wid & 3) * 32;
    const int g = lane >> 2, t = lane & 3;

    const int arow = (lane & 15);
    const int asel = (lane >> 4) * 4;
    const int brow = (lane & 7);
    const int bsel = ((lane >> 3) & 1) * 4;

    float c[4][4][4] = {};

    gemm_issue(sb, 0, 2 * TILE_W, A, W, m0, n0, 0, tid);
    CP_COMMIT();

    const int NT = DIM / 64;   // 16
    #pragma unroll 1
    for (int kt = 0; kt < NT; kt++) {
        const int buf = kt & 1;
        if (kt + 1 < NT) {
            gemm_issue(sb, (kt + 1 & 1) * TILE_W, (2 + (kt + 1 & 1)) * TILE_W,
                       A, W, m0, n0, (kt + 1) * 64, tid);
            CP_COMMIT();
            CP_WAIT(1);
        } else {
            CP_WAIT(0);
        }
        __syncthreads();

        const int ab = buf * TILE_W, bb = (2 + buf) * TILE_W;
        #pragma unroll
        for (int ks = 0; ks < 4; ks++) {
            uint32_t af[4][4], bf[4][2];
            #pragma unroll
            for (int mt = 0; mt < 4; mt++)
                ldsm_x4(af[mt], sb + 4u * (ab + (wm + mt * 16 + arow) * SKW + ks * 8 + asel));
            #pragma unroll
            for (int nt = 0; nt < 4; nt++)
                ldsm_x2(bf[nt], sb + 4u * (bb + (wn + nt * 8 + brow) * SKW + ks * 8 + bsel));
            #pragma unroll
            for (int mt = 0; mt < 4; mt++)
                #pragma unroll
                for (int nt = 0; nt < 4; nt++)
                    mma16(c[mt][nt], af[mt], bf[nt]);
        }
        __syncthreads();
    }

    // Epilogue
    #pragma unroll
    for (int mt = 0; mt < 4; mt++) {
        #pragma unroll
        for (int nt = 0; nt < 4; nt++) {
            const int n = n0 + wn + nt * 8 + 2 * t;
            const float2 bb2 = *(const float2*)&bias[n];
            #pragma unroll
            for (int rr = 0; rr < 2; rr++) {
                const int m = m0 + wm + mt * 16 + g + rr * 8;
                float vx = (c[mt][nt][rr * 2 + 0] + bb2.x) * scale;
                float vy = (c[mt][nt][rr * 2 + 1] + bb2.y) * scale;
                if (OUT_HALF) {
                    uint32_t pv = h2(vx, vy);
                    size_t off;
                    if (scatter) {
                        int b = m >> 11, ts = m & 2047;
                        int h = n >> 6, d = n & 63;
                        off = (size_t)(((b * NH + h) * QLEN) + ts) * DH + d;
                    } else {
                        off = (size_t)m * DIM + n;
                    }
                    *(uint32_t*)((__half*)out + off) = pv;
                } else {
                    float2 v; v.x = vx; v.y = vy;
                    *(float2*)((float*)out + (size_t)m * DIM + n) = v;
                }
            }
        }
    }
}

__global__ __launch_bounds__(256, 2) void gemm_qkv(
    const float* __restrict__ bq, const float* __restrict__ bk,
    const float* __restrict__ bv)
{
    const int z = blockIdx.z;
    const __half* W   = g_wh[z];
    const float* B    = (z == 0) ? bq : (z == 1) ? bk : bv;
    __half* out       = (z == 0) ? g_qh : (z == 1) ? g_kh : g_vh;
    const float scale = (z == 0) ? 0.125f : 1.0f;
    gemm_body_h<1>(g_xh, W, B, out, scale, 1);
}

__global__ __launch_bounds__(256, 2) void gemm_out(
    const float* __restrict__ bo, float* __restrict__ out)
{
    gemm_body_h<0>(g_ctxh, g_wh[3], bo, out, 1.0f, 0);
}

// ---------------------------------------------------------------------------
// fp16 flash attention, f16x2 softmax exp. Block: 128 q, 4 warps (32q x 64k).
// ---------------------------------------------------------------------------
#define SKQ 36
#define QOFF  0
#define KOFF  (128 * SKQ)
#define VOFF  (KOFF + 64 * SKQ)
#define MBOFF (VOFF + 64 * SKQ)
#define ATTN_WORDS (MBOFF + 64)

__global__ __launch_bounds__(128, 2) void attn_h(const int* __restrict__ mask)
{
    __shared__ __align__(16) uint32_t sm[ATTN_WORDS];
    float* mb = (float*)(sm + MBOFF);
    const uint32_t sb = smem_u32(sm);

    const int bh = blockIdx.y, b = bh >> 4, h = bh & 15;
    const int q0 = blockIdx.x * 128;
    const int tid = threadIdx.x, lane = tid & 31, wid = tid >> 5;
    const int g = lane >> 2, t = lane & 3;
    const int qw = wid * 32;
    const float L2E = 1.4426950408889634f;

    const __half* Qg = g_qh + (size_t)bh * QLEN * DH;
    const __half* Kg = g_kh + (size_t)bh * QLEN * DH;
    const __half* Vg = g_vh + (size_t)bh * QLEN * DH;

    const int arow = (lane & 15);
    const int asel = (lane >> 4) * 4;
    const int brow = (lane & 7);
    const int bsel = ((lane >> 3) & 1) * 4;
    const int vrow = (lane & 7) + ((lane >> 3) & 1) * 8;

    // Stage Q, pull fragments to registers.
    #pragma unroll
    for (int l = 0; l < 8; l++) {
        int idx = tid + l * 128;
        int row = idx >> 3, ch = (idx & 7) * 8;
        *(uint4*)&sm[QOFF + row * SKQ + (ch >> 1)] =
            *(const uint4*)&Qg[(size_t)(q0 + row) * DH + ch];
    }
    __syncthreads();
    uint32_t qf[2][4][4];
    #pragma unroll
    for (int mt = 0; mt < 2; mt++)
        #pragma unroll
        for (int ks = 0; ks < 4; ks++)
            ldsm_x4(qf[mt][ks],
                    sb + 4u * (QOFF + (qw + mt * 16 + arow) * SKQ + ks * 8 + asel));

    float o[2][8][4] = {};
    float rm[2][2], rl[2][2];
    #pragma unroll
    for (int mt = 0; mt < 2; mt++)
        #pragma unroll
        for (int r = 0; r < 2; r++) { rm[mt][r] = -1e30f; rl[mt][r] = 0.0f; }

    #pragma unroll 1
    for (int kt = 0; kt < QLEN / 64; kt++) {
        const int kbase = kt * 64;
        __syncthreads();
        #pragma unroll
        for (int l = 0; l < 4; l++) {
            int idx = tid + l * 128;
            int row = idx >> 3, ch = (idx & 7) * 8;
            *(uint4*)&sm[KOFF + row * SKQ + (ch >> 1)] =
                *(const uint4*)&Kg[(size_t)(kbase + row) * DH + ch];
            *(uint4*)&sm[VOFF + row * SKQ + (ch >> 1)] =
                *(const uint4*)&Vg[(size_t)(kbase + row) * DH + ch];
        }
        if (tid < 64)
            mb[tid] = (mask[b * QLEN + kbase + tid] == 0) ? -1e30f : 0.0f;
        __syncthreads();

        // S = Q @ K^T
        float s[2][8][4] = {};
        #pragma unroll
        for (int ks = 0; ks < 4; ks++) {
            #pragma unroll
            for (int nt = 0; nt < 8; nt++) {
                uint32_t bf[2];
                ldsm_x2(bf, sb + 4u * (KOFF + (nt * 8 + brow) * SKQ + ks * 8 + bsel));
                mma16(s[0][nt], qf[0][ks], bf);
                mma16(s[1][nt], qf[1][ks], bf);
            }
        }

        // mask add
        #pragma unroll
        for (int nt = 0; nt < 8; nt++) {
            float b0 = mb[nt * 8 + 2 * t];
            float b1 = mb[nt * 8 + 2 * t + 1];
            #pragma unroll
            for (int mt = 0; mt < 2; mt++) {
                s[mt][nt][0] += b0; s[mt][nt][1] += b1;
                s[mt][nt][2] += b0; s[mt][nt][3] += b1;
            }
        }

        // online softmax with f16x2 exp2; p16 words ARE the PV A-fragments
        uint32_t p16[2][8][2];
        #pragma unroll
        for (int mt = 0; mt < 2; mt++) {
            #pragma unroll
            for (int r = 0; r < 2; r++) {
                float mx = -1e30f;
                #pragma unroll
                for (int nt = 0; nt < 8; nt++)
                    mx = fmaxf(mx, fmaxf(s[mt][nt][r * 2], s[mt][nt][r * 2 + 1]));
                mx = fmaxf(mx, __shfl_xor_sync(0xffffffffu, mx, 1));
                mx = fmaxf(mx, __shfl_xor_sync(0xffffffffu, mx, 2));
                float mnew  = fmaxf(rm[mt][r], mx);
                float alpha = __expf(rm[mt][r] - mnew);
                rm[mt][r] = mnew;
                const float mli = mnew * L2E;
                float rs = 0.0f;
                #pragma unroll
                for (int nt = 0; nt < 8; nt++) {
                    float t0 = fmaf(s[mt][nt][r * 2],     L2E, -mli);
                    float t1 = fmaf(s[mt][nt][r * 2 + 1], L2E, -mli);
                    uint32_t pe = ex2_h2(h2(t0, t1));
                    p16[mt][nt][r] = pe;
                    float2 f = __half22float2(*(__half2*)&pe);
                    rs += f.x + f.y;
                }
                rs += __shfl_xor_sync(0xffffffffu, rs, 1);
                rs += __shfl_xor_sync(0xffffffffu, rs, 2);
                rl[mt][r] = rl[mt][r] * alpha + rs;
                #pragma unroll
                for (int nt = 0; nt < 8; nt++) {
                    o[mt][nt][r * 2]     *= alpha;
                    o[mt][nt][r * 2 + 1] *= alpha;
                }
            }
        }

        // O += P @ V : A-fragments straight from p16; V via ldmatrix.trans
        #pragma unroll
        for (int ks = 0; ks < 4; ks++) {
            uint32_t af[2][4];
            #pragma unroll
            for (int mt = 0; mt < 2; mt++) {
                af[mt][0] = p16[mt][2 * ks][0];
                af[mt][1] = p16[mt][2 * ks][1];
                af[mt][2] = p16[mt][2 * ks + 1][0];
                af[mt][3] = p16[mt][2 * ks + 1][1];
            }
            #pragma unroll
            for (int nt = 0; nt < 8; nt++) {
                uint32_t bf[2];
                ldsm_x2t(bf, sb + 4u * (VOFF + (16 * ks + vrow) * SKQ + nt * 4));
                mma16(o[0][nt], af[0], bf);
                mma16(o[1][nt], af[1], bf);
            }
        }
    }

    // Epilogue: ctx fp16 [b, t, h*64 + d]
    #pragma unroll
    for (int mt = 0; mt < 2; mt++) {
        #pragma unroll
        for (int r = 0; r < 2; r++) {
            float inv = 1.0f / rl[mt][r];
            int row = q0 + qw + mt * 16 + g + r * 8;
            #pragma unroll
            for (int nt = 0; nt < 8; nt++) {
                uint32_t pv = h2(o[mt][nt][r * 2] * inv, o[mt][nt][r * 2 + 1] * inv);
                *(uint32_t*)&g_ctxh[(size_t)(b * QLEN + row) * DIM + h * DH + nt * 8 + 2 * t] = pv;
            }
        }
    }
}

// ---------------------------------------------------------------------------
extern "C" void kernel_launch(void* const* d_in, const int* in_sizes, int n_in,
                              void* d_out, int out_size)
{
    const float* x    = (const float*)d_in[0];
    const int*   mask = (const int*)  d_in[1];
    const float* wq   = (const float*)d_in[2];
    const float* bq   = (const float*)d_in[3];
    const float* wk   = (const float*)d_in[4];
    const float* bk   = (const float*)d_in[5];
    const float* wv   = (const float*)d_in[6];
    const float* bv   = (const float*)d_in[7];
    const float* wo   = (const float*)d_in[8];
    const float* bo   = (const float*)d_in[9];
    float* out = (float*)d_out;

    __half* xh;
    cudaGetSymbolAddress((void**)&xh, g_xh);

    cudaFuncSetAttribute(gemm_qkv,
                         cudaFuncAttributeMaxDynamicSharedMemorySize, GEMM_SMEM_BYTES);
    cudaFuncSetAttribute(gemm_out,
                         cudaFuncAttributeMaxDynamicSharedMemorySize, GEMM_SMEM_BYTES);

    f2h_kernel<<<MTOT * DIM / 2048, 256>>>(x, xh);
    dim3 gw(DIM * DIM / 2048, 4);
    f2h_w_kernel<<<gw, 256>>>(wq, wk, wv, wo);

    dim3 gq(DIM / 128, MTOT / 128, 3);
    gemm_qkv<<<gq, 256, GEMM_SMEM_BYTES>>>(bq, bk, bv);

    dim3 ga(QLEN / 128, BSZ * NH);
    attn_h<<<ga, 128>>>(mask);

    dim3 go(DIM / 128, MTOT / 128);
    gemm_out<<<go, 256, GEMM_SMEM_BYTES>>>(bo, out);
}

// round 10
// speedup vs baseline: 2.3612x; 1.0564x over previous
#include <cuda_runtime.h>
#include <cuda_fp16.h>
#include <stdint.h>

#define BSZ  4
#define QLEN 2048
#define DIM  1024
#define NH   16
#define DH   64
#define MTOT (BSZ * QLEN)   // 8192

// Scratch (allocation-free rule: __device__ globals) — fp16 dataflow
__device__ __half g_xh [MTOT * DIM];
__device__ __half g_wh [4][DIM * DIM];          // wq, wk, wv, wo
__device__ __half g_qh [BSZ * NH * QLEN * DH];
__device__ __half g_kh [BSZ * NH * QLEN * DH];
__device__ __half g_vh [BSZ * NH * QLEN * DH];
__device__ __half g_ctxh[MTOT * DIM];

__device__ __forceinline__ uint32_t smem_u32(const void* p) {
    uint32_t a;
    asm("{ .reg .u64 t; cvta.to.shared.u64 t, %1; cvt.u32.u64 %0, t; }"
        : "=r"(a) : "l"(p));
    return a;
}

// pack two f32 -> f16x2 (lo in low half)
__device__ __forceinline__ uint32_t h2(float lo, float hi) {
    uint32_t r;
    asm("cvt.rn.f16x2.f32 %0, %1, %2;" : "=r"(r) : "f"(hi), "f"(lo));
    return r;
}

// 2-wide exp2 in fp16 (one MUFU op for two values)
__device__ __forceinline__ uint32_t ex2_h2(uint32_t x) {
    uint32_t r;
    asm("ex2.approx.f16x2 %0, %1;" : "=r"(r) : "r"(x));
    return r;
}

__device__ __forceinline__ void mma16(float c[4], const uint32_t a[4], const uint32_t b[2]) {
    asm volatile(
        "mma.sync.aligned.m16n8k16.row.col.f32.f16.f16.f32 "
        "{%0,%1,%2,%3}, {%4,%5,%6,%7}, {%8,%9}, {%0,%1,%2,%3};\n"
        : "+f"(c[0]), "+f"(c[1]), "+f"(c[2]), "+f"(c[3])
        : "r"(a[0]), "r"(a[1]), "r"(a[2]), "r"(a[3]), "r"(b[0]), "r"(b[1]));
}

__device__ __forceinline__ void ldsm_x4(uint32_t r[4], uint32_t addr) {
    asm volatile("ldmatrix.sync.aligned.m8n8.x4.shared.b16 {%0,%1,%2,%3}, [%4];"
        : "=r"(r[0]), "=r"(r[1]), "=r"(r[2]), "=r"(r[3]) : "r"(addr));
}
__device__ __forceinline__ void ldsm_x2(uint32_t r[2], uint32_t addr) {
    asm volatile("ldmatrix.sync.aligned.m8n8.x2.shared.b16 {%0,%1}, [%2];"
        : "=r"(r[0]), "=r"(r[1]) : "r"(addr));
}
__device__ __forceinline__ void ldsm_x2t(uint32_t r[2], uint32_t addr) {
    asm volatile("ldmatrix.sync.aligned.m8n8.x2.trans.shared.b16 {%0,%1}, [%2];"
        : "=r"(r[0]), "=r"(r[1]) : "r"(addr));
}

__device__ __forceinline__ void cp16(uint32_t dst, const void* src) {
    asm volatile("cp.async.ca.shared.global [%0], [%1], 16;\n" :: "r"(dst), "l"(src));
}
#define CP_COMMIT() asm volatile("cp.async.commit_group;\n" ::: "memory")
#define CP_WAIT(n)  asm volatile("cp.async.wait_group %0;\n" :: "n"(n) : "memory")

// ---------------------------------------------------------------------------
// f32 -> f16 converts
// ---------------------------------------------------------------------------
__global__ __launch_bounds__(256) void f2h_kernel(
    const float* __restrict__ src, __half* __restrict__ dst)
{
    int i = (blockIdx.x * 256 + threadIdx.x) * 8;
    float4 a = *(const float4*)&src[i];
    float4 b = *(const float4*)&src[i + 4];
    uint4 u;
    u.x = h2(a.x, a.y); u.y = h2(a.z, a.w);
    u.z = h2(b.x, b.y); u.w = h2(b.z, b.w);
    *(uint4*)&dst[i] = u;
}

__global__ __launch_bounds__(256) void f2h_w_kernel(
    const float* __restrict__ w0, const float* __restrict__ w1,
    const float* __restrict__ w2, const float* __restrict__ w3)
{
    const float* src = (blockIdx.y == 0) ? w0 : (blockIdx.y == 1) ? w1
                     : (blockIdx.y == 2) ? w2 : w3;
    __half* dst = g_wh[blockIdx.y];
    int i = (blockIdx.x * 256 + threadIdx.x) * 8;
    float4 a = *(const float4*)&src[i];
    float4 b = *(const float4*)&src[i + 4];
    uint4 u;
    u.x = h2(a.x, a.y); u.y = h2(a.z, a.w);
    u.z = h2(b.x, b.y); u.w = h2(b.z, b.w);
    *(uint4*)&dst[i] = u;
}

// ---------------------------------------------------------------------------
// fp16 GEMM with cp.async (unchanged from round 9)
// ---------------------------------------------------------------------------
#define SKW 36
#define TILE_W (128 * SKW)
#define GEMM_WORDS (4 * TILE_W)
#define GEMM_SMEM_BYTES (GEMM_WORDS * 4)   // 73728

__device__ __forceinline__ void gemm_issue(
    uint32_t sb, int bufA, int bufB,
    const __half* __restrict__ A, const __half* __restrict__ W,
    int m0, int n0, int k0, int tid)
{
    #pragma unroll
    for (int l = 0; l < 4; l++) {
        int cc = tid + l * 256;
        int row = cc >> 3, ch = (cc & 7) * 8;
        uint32_t da = sb + 4u * (bufA + row * SKW + (ch >> 1));
        cp16(da, A + (size_t)(m0 + row) * DIM + k0 + ch);
        uint32_t db = sb + 4u * (bufB + row * SKW + (ch >> 1));
        cp16(db, W + (size_t)(n0 + row) * DIM + k0 + ch);
    }
}

template <int OUT_HALF>
__device__ __forceinline__ void gemm_body_h(
    const __half* __restrict__ A, const __half* __restrict__ W,
    const float* __restrict__ bias, void* __restrict__ out,
    float scale, int scatter)
{
    extern __shared__ uint32_t sm[];
    const uint32_t sb = smem_u32(sm);
    const int m0 = blockIdx.y * 128, n0 = blockIdx.x * 128;
    const int tid = threadIdx.x, lane = tid & 31, wid = tid >> 5;
    const int wm = (wid >> 2) * 64, wn = (wid & 3) * 32;
    const int g = lane >> 2, t = lane & 3;

    const int arow = (lane & 15);
    const int asel = (lane >> 4) * 4;
    const int brow = (lane & 7);
    const int bsel = ((lane >> 3) & 1) * 4;

    float c[4][4][4] = {};

    gemm_issue(sb, 0, 2 * TILE_W, A, W, m0, n0, 0, tid);
    CP_COMMIT();

    const int NT = DIM / 64;   // 16
    #pragma unroll 1
    for (int kt = 0; kt < NT; kt++) {
        const int buf = kt & 1;
        if (kt + 1 < NT) {
            gemm_issue(sb, (kt + 1 & 1) * TILE_W, (2 + (kt + 1 & 1)) * TILE_W,
                       A, W, m0, n0, (kt + 1) * 64, tid);
            CP_COMMIT();
            CP_WAIT(1);
        } else {
            CP_WAIT(0);
        }
        __syncthreads();

        const int ab = buf * TILE_W, bb = (2 + buf) * TILE_W;
        #pragma unroll
        for (int ks = 0; ks < 4; ks++) {
            uint32_t af[4][4], bf[4][2];
            #pragma unroll
            for (int mt = 0; mt < 4; mt++)
                ldsm_x4(af[mt], sb + 4u * (ab + (wm + mt * 16 + arow) * SKW + ks * 8 + asel));
            #pragma unroll
            for (int nt = 0; nt < 4; nt++)
                ldsm_x2(bf[nt], sb + 4u * (bb + (wn + nt * 8 + brow) * SKW + ks * 8 + bsel));
            #pragma unroll
            for (int mt = 0; mt < 4; mt++)
                #pragma unroll
                for (int nt = 0; nt < 4; nt++)
                    mma16(c[mt][nt], af[mt], bf[nt]);
        }
        __syncthreads();
    }

    #pragma unroll
    for (int mt = 0; mt < 4; mt++) {
        #pragma unroll
        for (int nt = 0; nt < 4; nt++) {
            const int n = n0 + wn + nt * 8 + 2 * t;
            const float2 bb2 = *(const float2*)&bias[n];
            #pragma unroll
            for (int rr = 0; rr < 2; rr++) {
                const int m = m0 + wm + mt * 16 + g + rr * 8;
                float vx = (c[mt][nt][rr * 2 + 0] + bb2.x) * scale;
                float vy = (c[mt][nt][rr * 2 + 1] + bb2.y) * scale;
                if (OUT_HALF) {
                    uint32_t pv = h2(vx, vy);
                    size_t off;
                    if (scatter) {
                        int b = m >> 11, ts = m & 2047;
                        int h = n >> 6, d = n & 63;
                        off = (size_t)(((b * NH + h) * QLEN) + ts) * DH + d;
                    } else {
                        off = (size_t)m * DIM + n;
                    }
                    *(uint32_t*)((__half*)out + off) = pv;
                } else {
                    float2 v; v.x = vx; v.y = vy;
                    *(float2*)((float*)out + (size_t)m * DIM + n) = v;
                }
            }
        }
    }
}

__global__ __launch_bounds__(256, 2) void gemm_qkv(
    const float* __restrict__ bq, const float* __restrict__ bk,
    const float* __restrict__ bv)
{
    const int z = blockIdx.z;
    const __half* W   = g_wh[z];
    const float* B    = (z == 0) ? bq : (z == 1) ? bk : bv;
    __half* out       = (z == 0) ? g_qh : (z == 1) ? g_kh : g_vh;
    const float scale = (z == 0) ? 0.125f : 1.0f;
    gemm_body_h<1>(g_xh, W, B, out, scale, 1);
}

__global__ __launch_bounds__(256, 2) void gemm_out(
    const float* __restrict__ bo, float* __restrict__ out)
{
    gemm_body_h<0>(g_ctxh, g_wh[3], bo, out, 1.0f, 0);
}

// ---------------------------------------------------------------------------
// fp16 flash attention, 256 threads / 8 warps (warp = 16q x 64k),
// cp.async double-buffered K/V tiles, f16x2 softmax exp.
// smem: K0,V0,K1,V1 (each 64x36 words) + mb[2][64].
// ---------------------------------------------------------------------------
#define SKQ 36
#define KVW (64 * SKQ)                 // 2304 words per buffer
#define K0OFF 0
#define V0OFF KVW
#define K1OFF (2 * KVW)
#define V1OFF (3 * KVW)
#define MB2OFF (4 * KVW)               // 9216
#define ATTN_WORDS (MB2OFF + 128)      // 9344 -> 37376 B

__global__ __launch_bounds__(256, 2) void attn_h(const int* __restrict__ mask)
{
    __shared__ __align__(16) uint32_t sm[ATTN_WORDS];
    float* mb2 = (float*)(sm + MB2OFF);
    const uint32_t sb = smem_u32(sm);

    const int bh = blockIdx.y, b = bh >> 4, h = bh & 15;
    const int q0 = blockIdx.x * 128;
    const int tid = threadIdx.x, lane = tid & 31, wid = tid >> 5;
    const int g = lane >> 2, t = lane & 3;
    const int qw = wid * 16;
    const float L2E = 1.4426950408889634f;

    const __half* Qg = g_qh + (size_t)bh * QLEN * DH;
    const __half* Kg = g_kh + (size_t)bh * QLEN * DH;
    const __half* Vg = g_vh + (size_t)bh * QLEN * DH;

    const int arow = (lane & 15);
    const int asel = (lane >> 4) * 4;
    const int brow = (lane & 7);
    const int bsel = ((lane >> 3) & 1) * 4;
    const int vrow = (lane & 7) + ((lane >> 3) & 1) * 8;

    // Stage Q (128x64) through K0||V0 (contiguous 128-row window at offset 0),
    // pull per-warp fragments to registers, then release the buffers.
    #pragma unroll
    for (int l = 0; l < 4; l++) {
        int idx = tid + l * 256;            // 0..1023
        int row = idx >> 3, ch = (idx & 7) * 8;
        *(uint4*)&sm[row * SKQ + (ch >> 1)] =
            *(const uint4*)&Qg[(size_t)(q0 + row) * DH + ch];
    }
    __syncthreads();
    uint32_t qf[4][4];
    #pragma unroll
    for (int ks = 0; ks < 4; ks++)
        ldsm_x4(qf[ks], sb + 4u * ((qw + arow) * SKQ + ks * 8 + asel));
    __syncthreads();

    // Prologue: issue tile 0 into K0/V0 + mask 0
    #pragma unroll
    for (int l = 0; l < 2; l++) {
        int idx = tid + l * 256;            // 0..511
        int row = idx >> 3, ch = (idx & 7) * 8;
        cp16(sb + 4u * (K0OFF + row * SKQ + (ch >> 1)),
             Kg + (size_t)row * DH + ch);
        cp16(sb + 4u * (V0OFF + row * SKQ + (ch >> 1)),
             Vg + (size_t)row * DH + ch);
    }
    if (tid < 64)
        mb2[tid] = (mask[b * QLEN + tid] == 0) ? -1e30f : 0.0f;
    CP_COMMIT();

    float o[8][4] = {};
    float rm[2] = {-1e30f, -1e30f}, rl[2] = {0.0f, 0.0f};

    const int NT = QLEN / 64;   // 32
    #pragma unroll 1
    for (int kt = 0; kt < NT; kt++) {
        const int buf = kt & 1;
        if (kt + 1 < NT) {
            const int nb = (kt + 1) & 1;
            const int kb2 = (kt + 1) * 64;
            #pragma unroll
            for (int l = 0; l < 2; l++) {
                int idx = tid + l * 256;
                int row = idx >> 3, ch = (idx & 7) * 8;
                cp16(sb + 4u * ((nb ? K1OFF : K0OFF) + row * SKQ + (ch >> 1)),
                     Kg + (size_t)(kb2 + row) * DH + ch);
                cp16(sb + 4u * ((nb ? V1OFF : V0OFF) + row * SKQ + (ch >> 1)),
                     Vg + (size_t)(kb2 + row) * DH + ch);
            }
            if (tid < 64)
                mb2[nb * 64 + tid] = (mask[b * QLEN + kb2 + tid] == 0) ? -1e30f : 0.0f;
            CP_COMMIT();
            CP_WAIT(1);
        } else {
            CP_WAIT(0);
        }
        __syncthreads();

        const int kof = buf ? K1OFF : K0OFF;
        const int vof = buf ? V1OFF : V0OFF;
        const float* mb = mb2 + buf * 64;

        // S = Q @ K^T  (warp: 16q x 64k)
        float s[8][4] = {};
        #pragma unroll
        for (int ks = 0; ks < 4; ks++) {
            #pragma unroll
            for (int nt = 0; nt < 8; nt++) {
                uint32_t bf[2];
                ldsm_x2(bf, sb + 4u * (kof + (nt * 8 + brow) * SKQ + ks * 8 + bsel));
                mma16(s[nt], qf[ks], bf);
            }
        }

        // mask add
        #pragma unroll
        for (int nt = 0; nt < 8; nt++) {
            float b0 = mb[nt * 8 + 2 * t];
            float b1 = mb[nt * 8 + 2 * t + 1];
            s[nt][0] += b0; s[nt][1] += b1;
            s[nt][2] += b0; s[nt][3] += b1;
        }

        // online softmax, f16x2 exp2; p16 words ARE the PV A-fragments
        uint32_t p16[8][2];
        #pragma unroll
        for (int r = 0; r < 2; r++) {
            float mx = -1e30f;
            #pragma unroll
            for (int nt = 0; nt < 8; nt++)
                mx = fmaxf(mx, fmaxf(s[nt][r * 2], s[nt][r * 2 + 1]));
            mx = fmaxf(mx, __shfl_xor_sync(0xffffffffu, mx, 1));
            mx = fmaxf(mx, __shfl_xor_sync(0xffffffffu, mx, 2));
            float mnew  = fmaxf(rm[r], mx);
            float alpha = __expf(rm[r] - mnew);
            rm[r] = mnew;
            const float mli = mnew * L2E;
            float rs = 0.0f;
            #pragma unroll
            for (int nt = 0; nt < 8; nt++) {
                float t0 = fmaf(s[nt][r * 2],     L2E, -mli);
                float t1 = fmaf(s[nt][r * 2 + 1], L2E, -mli);
                uint32_t pe = ex2_h2(h2(t0, t1));
                p16[nt][r] = pe;
                float2 f = __half22float2(*(__half2*)&pe);
                rs += f.x + f.y;
            }
            rs += __shfl_xor_sync(0xffffffffu, rs, 1);
            rs += __shfl_xor_sync(0xffffffffu, rs, 2);
            rl[r] = rl[r] * alpha + rs;
            #pragma unroll
            for (int nt = 0; nt < 8; nt++) {
                o[nt][r * 2]     *= alpha;
                o[nt][r * 2 + 1] *= alpha;
            }
        }

        // O += P @ V
        #pragma unroll
        for (int ks = 0; ks < 4; ks++) {
            uint32_t af[4];
            af[0] = p16[2 * ks][0];
            af[1] = p16[2 * ks][1];
            af[2] = p16[2 * ks + 1][0];
            af[3] = p16[2 * ks + 1][1];
            #pragma unroll
            for (int nt = 0; nt < 8; nt++) {
                uint32_t bf[2];
                ldsm_x2t(bf, sb + 4u * (vof + (16 * ks + vrow) * SKQ + nt * 4));
                mma16(o[nt], af, bf);
            }
        }
        __syncthreads();   // all reads of buf done before it's refilled
    }

    // Epilogue: ctx fp16 [b, t, h*64 + d]
    #pragma unroll
    for (int r = 0; r < 2; r++) {
        float inv = 1.0f / rl[r];
        int row = q0 + qw + g + r * 8;
        #pragma unroll
        for (int nt = 0; nt < 8; nt++) {
            uint32_t pv = h2(o[nt][r * 2] * inv, o[nt][r * 2 + 1] * inv);
            *(uint32_t*)&g_ctxh[(size_t)(b * QLEN + row) * DIM + h * DH + nt * 8 + 2 * t] = pv;
        }
    }
}

// ---------------------------------------------------------------------------
extern "C" void kernel_launch(void* const* d_in, const int* in_sizes, int n_in,
                              void* d_out, int out_size)
{
    const float* x    = (const float*)d_in[0];
    const int*   mask = (const int*)  d_in[1];
    const float* wq   = (const float*)d_in[2];
    const float* bq   = (const float*)d_in[3];
    const float* wk   = (const float*)d_in[4];
    const float* bk   = (const float*)d_in[5];
    const float* wv   = (const float*)d_in[6];
    const float* bv   = (const float*)d_in[7];
    const float* wo   = (const float*)d_in[8];
    const float* bo   = (const float*)d_in[9];
    float* out = (float*)d_out;

    __half* xh;
    cudaGetSymbolAddress((void**)&xh, g_xh);

    cudaFuncSetAttribute(gemm_qkv,
                         cudaFuncAttributeMaxDynamicSharedMemorySize, GEMM_SMEM_BYTES);
    cudaFuncSetAttribute(gemm_out,
                         cudaFuncAttributeMaxDynamicSharedMemorySize, GEMM_SMEM_BYTES);

    f2h_kernel<<<MTOT * DIM / 2048, 256>>>(x, xh);
    dim3 gw(DIM * DIM / 2048, 4);
    f2h_w_kernel<<<gw, 256>>>(wq, wk, wv, wo);

    dim3 gq(DIM / 128, MTOT / 128, 3);
    gemm_qkv<<<gq, 256, GEMM_SMEM_BYTES>>>(bq, bk, bv);

    dim3 ga(QLEN / 128, BSZ * NH);
    attn_h<<<ga, 256>>>(mask);

    dim3 go(DIM / 128, MTOT / 128);
    gemm_out<<<go, 256, GEMM_SMEM_BYTES>>>(bo, out);
}

// round 11
// speedup vs baseline: 2.4834x; 1.0518x over previous
#include <cuda_runtime.h>
#include <cuda_fp16.h>
#include <stdint.h>

#define BSZ  4
#define QLEN 2048
#define DIM  1024
#define NH   16
#define DH   64
#define MTOT (BSZ * QLEN)   // 8192

// Scratch (allocation-free rule: __device__ globals) — fp16 dataflow
__device__ __half g_xh [MTOT * DIM];
__device__ __half g_wh [4][DIM * DIM];          // wq, wk, wv, wo
__device__ __half g_qh [BSZ * NH * QLEN * DH];
__device__ __half g_kh [BSZ * NH * QLEN * DH];
__device__ __half g_vh [BSZ * NH * QLEN * DH];
__device__ __half g_ctxh[MTOT * DIM];

__device__ __forceinline__ uint32_t smem_u32(const void* p) {
    uint32_t a;
    asm("{ .reg .u64 t; cvta.to.shared.u64 t, %1; cvt.u32.u64 %0, t; }"
        : "=r"(a) : "l"(p));
    return a;
}

// pack two f32 -> f16x2 (lo in low half)
__device__ __forceinline__ uint32_t h2(float lo, float hi) {
    uint32_t r;
    asm("cvt.rn.f16x2.f32 %0, %1, %2;" : "=r"(r) : "f"(hi), "f"(lo));
    return r;
}

// 2-wide exp2 in fp16 (one MUFU op for two values)
__device__ __forceinline__ uint32_t ex2_h2(uint32_t x) {
    uint32_t r;
    asm("ex2.approx.f16x2 %0, %1;" : "=r"(r) : "r"(x));
    return r;
}

__device__ __forceinline__ void mma16(float c[4], const uint32_t a[4], const uint32_t b[2]) {
    asm volatile(
        "mma.sync.aligned.m16n8k16.row.col.f32.f16.f16.f32 "
        "{%0,%1,%2,%3}, {%4,%5,%6,%7}, {%8,%9}, {%0,%1,%2,%3};\n"
        : "+f"(c[0]), "+f"(c[1]), "+f"(c[2]), "+f"(c[3])
        : "r"(a[0]), "r"(a[1]), "r"(a[2]), "r"(a[3]), "r"(b[0]), "r"(b[1]));
}

__device__ __forceinline__ void ldsm_x4(uint32_t r[4], uint32_t addr) {
    asm volatile("ldmatrix.sync.aligned.m8n8.x4.shared.b16 {%0,%1,%2,%3}, [%4];"
        : "=r"(r[0]), "=r"(r[1]), "=r"(r[2]), "=r"(r[3]) : "r"(addr));
}
__device__ __forceinline__ void ldsm_x4t(uint32_t r[4], uint32_t addr) {
    asm volatile("ldmatrix.sync.aligned.m8n8.x4.trans.shared.b16 {%0,%1,%2,%3}, [%4];"
        : "=r"(r[0]), "=r"(r[1]), "=r"(r[2]), "=r"(r[3]) : "r"(addr));
}

__device__ __forceinline__ void cp16(uint32_t dst, const void* src) {
    asm volatile("cp.async.ca.shared.global [%0], [%1], 16;\n" :: "r"(dst), "l"(src));
}
#define CP_COMMIT() asm volatile("cp.async.commit_group;\n" ::: "memory")
#define CP_WAIT(n)  asm volatile("cp.async.wait_group %0;\n" :: "n"(n) : "memory")

// ---------------------------------------------------------------------------
// f32 -> f16 converts
// ---------------------------------------------------------------------------
__global__ __launch_bounds__(256) void f2h_kernel(
    const float* __restrict__ src, __half* __restrict__ dst)
{
    int i = (blockIdx.x * 256 + threadIdx.x) * 8;
    float4 a = *(const float4*)&src[i];
    float4 b = *(const float4*)&src[i + 4];
    uint4 u;
    u.x = h2(a.x, a.y); u.y = h2(a.z, a.w);
    u.z = h2(b.x, b.y); u.w = h2(b.z, b.w);
    *(uint4*)&dst[i] = u;
}

__global__ __launch_bounds__(256) void f2h_w_kernel(
    const float* __restrict__ w0, const float* __restrict__ w1,
    const float* __restrict__ w2, const float* __restrict__ w3)
{
    const float* src = (blockIdx.y == 0) ? w0 : (blockIdx.y == 1) ? w1
                     : (blockIdx.y == 2) ? w2 : w3;
    __half* dst = g_wh[blockIdx.y];
    int i = (blockIdx.x * 256 + threadIdx.x) * 8;
    float4 a = *(const float4*)&src[i];
    float4 b = *(const float4*)&src[i + 4];
    uint4 u;
    u.x = h2(a.x, a.y); u.y = h2(a.z, a.w);
    u.z = h2(b.x, b.y); u.w = h2(b.z, b.w);
    *(uint4*)&dst[i] = u;
}

// ---------------------------------------------------------------------------
// fp16 GEMM with cp.async, x4 B-fragment loads.
// BM=BN=128, BK=64, 256 threads, 8 warps (2m x 4n), warp tile 64x32.
// ---------------------------------------------------------------------------
#define SKW 36
#define TILE_W (128 * SKW)
#define GEMM_WORDS (4 * TILE_W)
#define GEMM_SMEM_BYTES (GEMM_WORDS * 4)   // 73728

__device__ __forceinline__ void gemm_issue(
    uint32_t sb, int bufA, int bufB,
    const __half* __restrict__ A, const __half* __restrict__ W,
    int m0, int n0, int k0, int tid)
{
    #pragma unroll
    for (int l = 0; l < 4; l++) {
        int cc = tid + l * 256;
        int row = cc >> 3, ch = (cc & 7) * 8;
        uint32_t da = sb + 4u * (bufA + row * SKW + (ch >> 1));
        cp16(da, A + (size_t)(m0 + row) * DIM + k0 + ch);
        uint32_t db = sb + 4u * (bufB + row * SKW + (ch >> 1));
        cp16(db, W + (size_t)(n0 + row) * DIM + k0 + ch);
    }
}

template <int OUT_HALF>
__device__ __forceinline__ void gemm_body_h(
    const __half* __restrict__ A, const __half* __restrict__ W,
    const float* __restrict__ bias, void* __restrict__ out,
    float scale, int scatter)
{
    extern __shared__ uint32_t sm[];
    const uint32_t sb = smem_u32(sm);
    const int m0 = blockIdx.y * 128, n0 = blockIdx.x * 128;
    const int tid = threadIdx.x, lane = tid & 31, wid = tid >> 5;
    const int wm = (wid >> 2) * 64, wn = (wid & 3) * 32;
    const int g = lane >> 2, t = lane & 3;

    const int arow = (lane & 15);
    const int asel = (lane >> 4) * 4;
    // x4 B-load lane mapping: pairs of n-groups
    const int bx4row = ((lane >> 4) & 1) * 8 + (lane & 7);
    const int bx4sel = ((lane >> 3) & 1) * 4;

    float c[4][4][4] = {};

    gemm_issue(sb, 0, 2 * TILE_W, A, W, m0, n0, 0, tid);
    CP_COMMIT();

    const int NT = DIM / 64;   // 16
    #pragma unroll 1
    for (int kt = 0; kt < NT; kt++) {
        const int buf = kt & 1;
        if (kt + 1 < NT) {
            gemm_issue(sb, (kt + 1 & 1) * TILE_W, (2 + (kt + 1 & 1)) * TILE_W,
                       A, W, m0, n0, (kt + 1) * 64, tid);
            CP_COMMIT();
            CP_WAIT(1);
        } else {
            CP_WAIT(0);
        }
        __syncthreads();

        const int ab = buf * TILE_W, bb = (2 + buf) * TILE_W;
        #pragma unroll
        for (int ks = 0; ks < 4; ks++) {
            uint32_t af[4][4], bf[2][4];   // bf[ntp] covers nt=2ntp,2ntp+1
            #pragma unroll
            for (int mt = 0; mt < 4; mt++)
                ldsm_x4(af[mt], sb + 4u * (ab + (wm + mt * 16 + arow) * SKW + ks * 8 + asel));
            #pragma unroll
            for (int ntp = 0; ntp < 2; ntp++)
                ldsm_x4(bf[ntp], sb + 4u * (bb + (wn + ntp * 16 + bx4row) * SKW + ks * 8 + bx4sel));
            #pragma unroll
            for (int mt = 0; mt < 4; mt++)
                #pragma unroll
                for (int nt = 0; nt < 4; nt++)
                    mma16(c[mt][nt], af[mt], &bf[nt >> 1][(nt & 1) * 2]);
        }
        __syncthreads();
    }

    #pragma unroll
    for (int mt = 0; mt < 4; mt++) {
        #pragma unroll
        for (int nt = 0; nt < 4; nt++) {
            const int n = n0 + wn + nt * 8 + 2 * t;
            const float2 bb2 = *(const float2*)&bias[n];
            #pragma unroll
            for (int rr = 0; rr < 2; rr++) {
                const int m = m0 + wm + mt * 16 + g + rr * 8;
                float vx = (c[mt][nt][rr * 2 + 0] + bb2.x) * scale;
                float vy = (c[mt][nt][rr * 2 + 1] + bb2.y) * scale;
                if (OUT_HALF) {
                    uint32_t pv = h2(vx, vy);
                    size_t off;
                    if (scatter) {
                        int b = m >> 11, ts = m & 2047;
                        int h = n >> 6, d = n & 63;
                        off = (size_t)(((b * NH + h) * QLEN) + ts) * DH + d;
                    } else {
                        off = (size_t)m * DIM + n;
                    }
                    *(uint32_t*)((__half*)out + off) = pv;
                } else {
                    float2 v; v.x = vx; v.y = vy;
                    *(float2*)((float*)out + (size_t)m * DIM + n) = v;
                }
            }
        }
    }
}

__global__ __launch_bounds__(256, 2) void gemm_qkv(
    const float* __restrict__ bq, const float* __restrict__ bk,
    const float* __restrict__ bv)
{
    const int z = blockIdx.z;
    const __half* W   = g_wh[z];
    const float* B    = (z == 0) ? bq : (z == 1) ? bk : bv;
    __half* out       = (z == 0) ? g_qh : (z == 1) ? g_kh : g_vh;
    const float scale = (z == 0) ? 0.125f : 1.0f;
    gemm_body_h<1>(g_xh, W, B, out, scale, 1);
}

__global__ __launch_bounds__(256, 2) void gemm_out(
    const float* __restrict__ bo, float* __restrict__ out)
{
    gemm_body_h<0>(g_ctxh, g_wh[3], bo, out, 1.0f, 0);
}

// ---------------------------------------------------------------------------
// fp16 flash attention, 256 threads / 8 warps (warp = 16q x 64k).
// Triple-buffered cp.async K/V (+mask), prefetch distance 2, ONE sync/tile.
// x4 ldmatrix fragments. smem: K0..K2, V0..V2 (64x36 words each) + mb[3][64].
// ---------------------------------------------------------------------------
#define SKQ 36
#define KVW (64 * SKQ)                 // 2304 words per buffer
#define MB3OFF (6 * KVW)               // 13824
#define ATTN_WORDS (MB3OFF + 192)      // 14016 -> 56064 B

__global__ __launch_bounds__(256, 2) void attn_h(const int* __restrict__ mask)
{
    __shared__ __align__(16) uint32_t sm[ATTN_WORDS];
    float* mb3 = (float*)(sm + MB3OFF);
    const uint32_t sb = smem_u32(sm);

    const int bh = blockIdx.y, b = bh >> 4, h = bh & 15;
    const int q0 = blockIdx.x * 128;
    const int tid = threadIdx.x, lane = tid & 31, wid = tid >> 5;
    const int g = lane >> 2, t = lane & 3;
    const int qw = wid * 16;
    const float L2E = 1.4426950408889634f;

    const __half* Qg = g_qh + (size_t)bh * QLEN * DH;
    const __half* Kg = g_kh + (size_t)bh * QLEN * DH;
    const __half* Vg = g_vh + (size_t)bh * QLEN * DH;

    const int arow = (lane & 15);
    const int asel = (lane >> 4) * 4;
    // K x4: pairs of key-groups; V x4 trans: pairs of d-groups
    const int kx4row = ((lane >> 4) & 1) * 8 + (lane & 7);
    const int kx4sel = ((lane >> 3) & 1) * 4;
    const int vrow   = (lane & 7) + ((lane >> 3) & 1) * 8;
    const int vx4c   = (lane >> 4) * 4;

    // Stage Q (128x64) through K0||K1 (contiguous window at offset 0),
    // pull per-warp fragments to registers, then release the buffers.
    #pragma unroll
    for (int l = 0; l < 4; l++) {
        int idx = tid + l * 256;
        int row = idx >> 3, ch = (idx & 7) * 8;
        *(uint4*)&sm[row * SKQ + (ch >> 1)] =
            *(const uint4*)&Qg[(size_t)(q0 + row) * DH + ch];
    }
    __syncthreads();
    uint32_t qf[4][4];
    #pragma unroll
    for (int ks = 0; ks < 4; ks++)
        ldsm_x4(qf[ks], sb + 4u * ((qw + arow) * SKQ + ks * 8 + asel));
    __syncthreads();

    // Prologue: issue tiles 0 and 1 (prefetch distance 2)
    #pragma unroll
    for (int pt = 0; pt < 2; pt++) {
        #pragma unroll
        for (int l = 0; l < 2; l++) {
            int idx = tid + l * 256;
            int row = idx >> 3, ch = (idx & 7) * 8;
            cp16(sb + 4u * (pt * KVW + row * SKQ + (ch >> 1)),
                 Kg + (size_t)(pt * 64 + row) * DH + ch);
            cp16(sb + 4u * ((3 + pt) * KVW + row * SKQ + (ch >> 1)),
                 Vg + (size_t)(pt * 64 + row) * DH + ch);
        }
        if (tid < 64)
            mb3[pt * 64 + tid] = (mask[b * QLEN + pt * 64 + tid] == 0) ? -1e30f : 0.0f;
        CP_COMMIT();
    }

    float o[8][4] = {};
    float rm[2] = {-1e30f, -1e30f}, rl[2] = {0.0f, 0.0f};

    const int NT = QLEN / 64;   // 32
    int cur = 0, iss = 2;
    #pragma unroll 1
    for (int kt = 0; kt < NT; kt++) {
        if (kt + 2 < NT) { CP_WAIT(1); } else { CP_WAIT(0); }
        __syncthreads();    // tile kt visible; buffer iss free (last read kt-1)

        if (kt + 2 < NT) {
            const int kb2 = (kt + 2) * 64;
            #pragma unroll
            for (int l = 0; l < 2; l++) {
                int idx = tid + l * 256;
                int row = idx >> 3, ch = (idx & 7) * 8;
                cp16(sb + 4u * (iss * KVW + row * SKQ + (ch >> 1)),
                     Kg + (size_t)(kb2 + row) * DH + ch);
                cp16(sb + 4u * ((3 + iss) * KVW + row * SKQ + (ch >> 1)),
                     Vg + (size_t)(kb2 + row) * DH + ch);
            }
            if (tid < 64)
                mb3[iss * 64 + tid] = (mask[b * QLEN + kb2 + tid] == 0) ? -1e30f : 0.0f;
            CP_COMMIT();
        }

        const int kof = cur * KVW;
        const int vof = (3 + cur) * KVW;
        const float* mb = mb3 + cur * 64;

        // S = Q @ K^T  (warp: 16q x 64k), x4 B-fragment loads
        float s[8][4] = {};
        #pragma unroll
        for (int ks = 0; ks < 4; ks++) {
            #pragma unroll
            for (int ntp = 0; ntp < 4; ntp++) {
                uint32_t bf[4];
                ldsm_x4(bf, sb + 4u * (kof + (ntp * 16 + kx4row) * SKQ + ks * 8 + kx4sel));
                mma16(s[2 * ntp],     qf[ks], &bf[0]);
                mma16(s[2 * ntp + 1], qf[ks], &bf[2]);
            }
        }

        // mask add
        #pragma unroll
        for (int nt = 0; nt < 8; nt++) {
            float b0 = mb[nt * 8 + 2 * t];
            float b1 = mb[nt * 8 + 2 * t + 1];
            s[nt][0] += b0; s[nt][1] += b1;
            s[nt][2] += b0; s[nt][3] += b1;
        }

        // online softmax, f16x2 exp2; p16 words ARE the PV A-fragments
        uint32_t p16[8][2];
        #pragma unroll
        for (int r = 0; r < 2; r++) {
            float mx = -1e30f;
            #pragma unroll
            for (int nt = 0; nt < 8; nt++)
                mx = fmaxf(mx, fmaxf(s[nt][r * 2], s[nt][r * 2 + 1]));
            mx = fmaxf(mx, __shfl_xor_sync(0xffffffffu, mx, 1));
            mx = fmaxf(mx, __shfl_xor_sync(0xffffffffu, mx, 2));
            float mnew  = fmaxf(rm[r], mx);
            float alpha = __expf(rm[r] - mnew);
            rm[r] = mnew;
            const float mli = mnew * L2E;
            float rs = 0.0f;
            #pragma unroll
            for (int nt = 0; nt < 8; nt++) {
                float t0 = fmaf(s[nt][r * 2],     L2E, -mli);
                float t1 = fmaf(s[nt][r * 2 + 1], L2E, -mli);
                uint32_t pe = ex2_h2(h2(t0, t1));
                p16[nt][r] = pe;
                float2 f = __half22float2(*(__half2*)&pe);
                rs += f.x + f.y;
            }
            rs += __shfl_xor_sync(0xffffffffu, rs, 1);
            rs += __shfl_xor_sync(0xffffffffu, rs, 2);
            rl[r] = rl[r] * alpha + rs;
            #pragma unroll
            for (int nt = 0; nt < 8; nt++) {
                o[nt][r * 2]     *= alpha;
                o[nt][r * 2 + 1] *= alpha;
            }
        }

        // O += P @ V  (x4 trans V-fragment loads: two d-groups per instr)
        #pragma unroll
        for (int ks = 0; ks < 4; ks++) {
            uint32_t af[4];
            af[0] = p16[2 * ks][0];
            af[1] = p16[2 * ks][1];
            af[2] = p16[2 * ks + 1][0];
            af[3] = p16[2 * ks + 1][1];
            #pragma unroll
            for (int ntp = 0; ntp < 4; ntp++) {
                uint32_t bf[4];
                ldsm_x4t(bf, sb + 4u * (vof + (16 * ks + vrow) * SKQ + ntp * 8 + vx4c));
                mma16(o[2 * ntp],     af, &bf[0]);
                mma16(o[2 * ntp + 1], af, &bf[2]);
            }
        }

        cur = (cur == 2) ? 0 : cur + 1;
        iss = (iss == 2) ? 0 : iss + 1;
    }

    // Epilogue: ctx fp16 [b, t, h*64 + d]
    #pragma unroll
    for (int r = 0; r < 2; r++) {
        float inv = 1.0f / rl[r];
        int row = q0 + qw + g + r * 8;
        #pragma unroll
        for (int nt = 0; nt < 8; nt++) {
            uint32_t pv = h2(o[nt][r * 2] * inv, o[nt][r * 2 + 1] * inv);
            *(uint32_t*)&g_ctxh[(size_t)(b * QLEN + row) * DIM + h * DH + nt * 8 + 2 * t] = pv;
        }
    }
}

// ---------------------------------------------------------------------------
extern "C" void kernel_launch(void* const* d_in, const int* in_sizes, int n_in,
                              void* d_out, int out_size)
{
    const float* x    = (const float*)d_in[0];
    const int*   mask = (const int*)  d_in[1];
    const float* wq   = (const float*)d_in[2];
    const float* bq   = (const float*)d_in[3];
    const float* wk   = (const float*)d_in[4];
    const float* bk   = (const float*)d_in[5];
    const float* wv   = (const float*)d_in[6];
    const float* bv   = (const float*)d_in[7];
    const float* wo   = (const float*)d_in[8];
    const float* bo   = (const float*)d_in[9];
    float* out = (float*)d_out;

    __half* xh;
    cudaGetSymbolAddress((void**)&xh, g_xh);

    cudaFuncSetAttribute(gemm_qkv,
                         cudaFuncAttributeMaxDynamicSharedMemorySize, GEMM_SMEM_BYTES);
    cudaFuncSetAttribute(gemm_out,
                         cudaFuncAttributeMaxDynamicSharedMemorySize, GEMM_SMEM_BYTES);

    f2h_kernel<<<MTOT * DIM / 2048, 256>>>(x, xh);
    dim3 gw(DIM * DIM / 2048, 4);
    f2h_w_kernel<<<gw, 256>>>(wq, wk, wv, wo);

    dim3 gq(DIM / 128, MTOT / 128, 3);
    gemm_qkv<<<gq, 256, GEMM_SMEM_BYTES>>>(bq, bk, bv);

    dim3 ga(QLEN / 128, BSZ * NH);
    attn_h<<<ga, 256>>>(mask);

    dim3 go(DIM / 128, MTOT / 128);
    gemm_out<<<go, 256, GEMM_SMEM_BYTES>>>(bo, out);
}

// round 12
// speedup vs baseline: 2.5236x; 1.0162x over previous
#include <cuda_runtime.h>
#include <cuda_fp16.h>
#include <stdint.h>

#define BSZ  4
#define QLEN 2048
#define DIM  1024
#define NH   16
#define DH   64
#define MTOT (BSZ * QLEN)   // 8192

// Scratch (allocation-free rule: __device__ globals) — fp16 dataflow
__device__ __half g_xh [MTOT * DIM];
__device__ __half g_wh [4][DIM * DIM];          // wq, wk, wv, wo
__device__ __half g_qh [BSZ * NH * QLEN * DH];
__device__ __half g_kh [BSZ * NH * QLEN * DH];
__device__ __half g_vh [BSZ * NH * QLEN * DH];
__device__ __half g_ctxh[MTOT * DIM];

__device__ __forceinline__ uint32_t smem_u32(const void* p) {
    uint32_t a;
    asm("{ .reg .u64 t; cvta.to.shared.u64 t, %1; cvt.u32.u64 %0, t; }"
        : "=r"(a) : "l"(p));
    return a;
}

// pack two f32 -> f16x2 (lo in low half)
__device__ __forceinline__ uint32_t h2(float lo, float hi) {
    uint32_t r;
    asm("cvt.rn.f16x2.f32 %0, %1, %2;" : "=r"(r) : "f"(hi), "f"(lo));
    return r;
}

// 2-wide exp2 in fp16 (one MUFU op for two values)
__device__ __forceinline__ uint32_t ex2_h2(uint32_t x) {
    uint32_t r;
    asm("ex2.approx.f16x2 %0, %1;" : "=r"(r) : "r"(x));
    return r;
}

__device__ __forceinline__ void mma16(float c[4], const uint32_t a[4], const uint32_t b[2]) {
    asm volatile(
        "mma.sync.aligned.m16n8k16.row.col.f32.f16.f16.f32 "
        "{%0,%1,%2,%3}, {%4,%5,%6,%7}, {%8,%9}, {%0,%1,%2,%3};\n"
        : "+f"(c[0]), "+f"(c[1]), "+f"(c[2]), "+f"(c[3])
        : "r"(a[0]), "r"(a[1]), "r"(a[2]), "r"(a[3]), "r"(b[0]), "r"(b[1]));
}

__device__ __forceinline__ void ldsm_x4(uint32_t r[4], uint32_t addr) {
    asm volatile("ldmatrix.sync.aligned.m8n8.x4.shared.b16 {%0,%1,%2,%3}, [%4];"
        : "=r"(r[0]), "=r"(r[1]), "=r"(r[2]), "=r"(r[3]) : "r"(addr));
}
__device__ __forceinline__ void ldsm_x4t(uint32_t r[4], uint32_t addr) {
    asm volatile("ldmatrix.sync.aligned.m8n8.x4.trans.shared.b16 {%0,%1,%2,%3}, [%4];"
        : "=r"(r[0]), "=r"(r[1]), "=r"(r[2]), "=r"(r[3]) : "r"(addr));
}

__device__ __forceinline__ void cp16(uint32_t dst, const void* src) {
    asm volatile("cp.async.ca.shared.global [%0], [%1], 16;\n" :: "r"(dst), "l"(src));
}
#define CP_COMMIT() asm volatile("cp.async.commit_group;\n" ::: "memory")
#define CP_WAIT(n)  asm volatile("cp.async.wait_group %0;\n" :: "n"(n) : "memory")

// ---------------------------------------------------------------------------
// f32 -> f16 converts
// ---------------------------------------------------------------------------
__global__ __launch_bounds__(256) void f2h_kernel(
    const float* __restrict__ src, __half* __restrict__ dst)
{
    int i = (blockIdx.x * 256 + threadIdx.x) * 8;
    float4 a = *(const float4*)&src[i];
    float4 b = *(const float4*)&src[i + 4];
    uint4 u;
    u.x = h2(a.x, a.y); u.y = h2(a.z, a.w);
    u.z = h2(b.x, b.y); u.w = h2(b.z, b.w);
    *(uint4*)&dst[i] = u;
}

__global__ __launch_bounds__(256) void f2h_w_kernel(
    const float* __restrict__ w0, const float* __restrict__ w1,
    const float* __restrict__ w2, const float* __restrict__ w3)
{
    const float* src = (blockIdx.y == 0) ? w0 : (blockIdx.y == 1) ? w1
                     : (blockIdx.y == 2) ? w2 : w3;
    __half* dst = g_wh[blockIdx.y];
    int i = (blockIdx.x * 256 + threadIdx.x) * 8;
    float4 a = *(const float4*)&src[i];
    float4 b = *(const float4*)&src[i + 4];
    uint4 u;
    u.x = h2(a.x, a.y); u.y = h2(a.z, a.w);
    u.z = h2(b.x, b.y); u.w = h2(b.z, b.w);
    *(uint4*)&dst[i] = u;
}

// ---------------------------------------------------------------------------
// fp16 GEMM with cp.async, x4 B-fragment loads (unchanged from round 11)
// ---------------------------------------------------------------------------
#define SKW 36
#define TILE_W (128 * SKW)
#define GEMM_WORDS (4 * TILE_W)
#define GEMM_SMEM_BYTES (GEMM_WORDS * 4)   // 73728

__device__ __forceinline__ void gemm_issue(
    uint32_t sb, int bufA, int bufB,
    const __half* __restrict__ A, const __half* __restrict__ W,
    int m0, int n0, int k0, int tid)
{
    #pragma unroll
    for (int l = 0; l < 4; l++) {
        int cc = tid + l * 256;
        int row = cc >> 3, ch = (cc & 7) * 8;
        uint32_t da = sb + 4u * (bufA + row * SKW + (ch >> 1));
        cp16(da, A + (size_t)(m0 + row) * DIM + k0 + ch);
        uint32_t db = sb + 4u * (bufB + row * SKW + (ch >> 1));
        cp16(db, W + (size_t)(n0 + row) * DIM + k0 + ch);
    }
}

template <int OUT_HALF>
__device__ __forceinline__ void gemm_body_h(
    const __half* __restrict__ A, const __half* __restrict__ W,
    const float* __restrict__ bias, void* __restrict__ out,
    float scale, int scatter)
{
    extern __shared__ uint32_t sm[];
    const uint32_t sb = smem_u32(sm);
    const int m0 = blockIdx.y * 128, n0 = blockIdx.x * 128;
    const int tid = threadIdx.x, lane = tid & 31, wid = tid >> 5;
    const int wm = (wid >> 2) * 64, wn = (wid & 3) * 32;
    const int g = lane >> 2, t = lane & 3;

    const int arow = (lane & 15);
    const int asel = (lane >> 4) * 4;
    const int bx4row = ((lane >> 4) & 1) * 8 + (lane & 7);
    const int bx4sel = ((lane >> 3) & 1) * 4;

    float c[4][4][4] = {};

    gemm_issue(sb, 0, 2 * TILE_W, A, W, m0, n0, 0, tid);
    CP_COMMIT();

    const int NT = DIM / 64;   // 16
    #pragma unroll 1
    for (int kt = 0; kt < NT; kt++) {
        const int buf = kt & 1;
        if (kt + 1 < NT) {
            gemm_issue(sb, (kt + 1 & 1) * TILE_W, (2 + (kt + 1 & 1)) * TILE_W,
                       A, W, m0, n0, (kt + 1) * 64, tid);
            CP_COMMIT();
            CP_WAIT(1);
        } else {
            CP_WAIT(0);
        }
        __syncthreads();

        const int ab = buf * TILE_W, bb = (2 + buf) * TILE_W;
        #pragma unroll
        for (int ks = 0; ks < 4; ks++) {
            uint32_t af[4][4], bf[2][4];
            #pragma unroll
            for (int mt = 0; mt < 4; mt++)
                ldsm_x4(af[mt], sb + 4u * (ab + (wm + mt * 16 + arow) * SKW + ks * 8 + asel));
            #pragma unroll
            for (int ntp = 0; ntp < 2; ntp++)
                ldsm_x4(bf[ntp], sb + 4u * (bb + (wn + ntp * 16 + bx4row) * SKW + ks * 8 + bx4sel));
            #pragma unroll
            for (int mt = 0; mt < 4; mt++)
                #pragma unroll
                for (int nt = 0; nt < 4; nt++)
                    mma16(c[mt][nt], af[mt], &bf[nt >> 1][(nt & 1) * 2]);
        }
        __syncthreads();
    }

    #pragma unroll
    for (int mt = 0; mt < 4; mt++) {
        #pragma unroll
        for (int nt = 0; nt < 4; nt++) {
            const int n = n0 + wn + nt * 8 + 2 * t;
            const float2 bb2 = *(const float2*)&bias[n];
            #pragma unroll
            for (int rr = 0; rr < 2; rr++) {
                const int m = m0 + wm + mt * 16 + g + rr * 8;
                float vx = (c[mt][nt][rr * 2 + 0] + bb2.x) * scale;
                float vy = (c[mt][nt][rr * 2 + 1] + bb2.y) * scale;
                if (OUT_HALF) {
                    uint32_t pv = h2(vx, vy);
                    size_t off;
                    if (scatter) {
                        int b = m >> 11, ts = m & 2047;
                        int h = n >> 6, d = n & 63;
                        off = (size_t)(((b * NH + h) * QLEN) + ts) * DH + d;
                    } else {
                        off = (size_t)m * DIM + n;
                    }
                    *(uint32_t*)((__half*)out + off) = pv;
                } else {
                    float2 v; v.x = vx; v.y = vy;
                    *(float2*)((float*)out + (size_t)m * DIM + n) = v;
                }
            }
        }
    }
}

__global__ __launch_bounds__(256, 2) void gemm_qkv(
    const float* __restrict__ bq, const float* __restrict__ bk,
    const float* __restrict__ bv)
{
    const int z = blockIdx.z;
    const __half* W   = g_wh[z];
    const float* B    = (z == 0) ? bq : (z == 1) ? bk : bv;
    __half* out       = (z == 0) ? g_qh : (z == 1) ? g_kh : g_vh;
    const float scale = (z == 0) ? 0.125f : 1.0f;
    gemm_body_h<1>(g_xh, W, B, out, scale, 1);
}

__global__ __launch_bounds__(256, 2) void gemm_out(
    const float* __restrict__ bo, float* __restrict__ out)
{
    gemm_body_h<0>(g_ctxh, g_wh[3], bo, out, 1.0f, 0);
}

// ---------------------------------------------------------------------------
// fp16 flash attention, 256 threads / 8 warps (warp = 16q x 64k).
// Triple-buffered cp.async K/V (+mask), prefetch distance 2, ONE sync/tile.
// Row-sums via ones-MMA (no scalar unpack, no sum shfl).
// ---------------------------------------------------------------------------
#define SKQ 36
#define KVW (64 * SKQ)                 // 2304 words per buffer
#define MB3OFF (6 * KVW)               // 13824
#define ATTN_WORDS (MB3OFF + 192)      // 14016 -> 56064 B

#define ONES_H2 0x3C003C00u            // (1.0h, 1.0h)

__global__ __launch_bounds__(256, 2) void attn_h(const int* __restrict__ mask)
{
    __shared__ __align__(16) uint32_t sm[ATTN_WORDS];
    float* mb3 = (float*)(sm + MB3OFF);
    const uint32_t sb = smem_u32(sm);

    const int bh = blockIdx.y, b = bh >> 4, h = bh & 15;
    const int q0 = blockIdx.x * 128;
    const int tid = threadIdx.x, lane = tid & 31, wid = tid >> 5;
    const int g = lane >> 2, t = lane & 3;
    const int qw = wid * 16;
    const float L2E = 1.4426950408889634f;

    const __half* Qg = g_qh + (size_t)bh * QLEN * DH;
    const __half* Kg = g_kh + (size_t)bh * QLEN * DH;
    const __half* Vg = g_vh + (size_t)bh * QLEN * DH;

    const int arow = (lane & 15);
    const int asel = (lane >> 4) * 4;
    const int kx4row = ((lane >> 4) & 1) * 8 + (lane & 7);
    const int kx4sel = ((lane >> 3) & 1) * 4;
    const int vrow   = (lane & 7) + ((lane >> 3) & 1) * 8;
    const int vx4c   = (lane >> 4) * 4;

    const uint32_t ones_bf[2] = {ONES_H2, ONES_H2};

    // Stage Q (128x64) through buffer window at offset 0, pull fragments.
    #pragma unroll
    for (int l = 0; l < 4; l++) {
        int idx = tid + l * 256;
        int row = idx >> 3, ch = (idx & 7) * 8;
        *(uint4*)&sm[row * SKQ + (ch >> 1)] =
            *(const uint4*)&Qg[(size_t)(q0 + row) * DH + ch];
    }
    __syncthreads();
    uint32_t qf[4][4];
    #pragma unroll
    for (int ks = 0; ks < 4; ks++)
        ldsm_x4(qf[ks], sb + 4u * ((qw + arow) * SKQ + ks * 8 + asel));
    __syncthreads();

    // Prologue: issue tiles 0 and 1 (prefetch distance 2)
    #pragma unroll
    for (int pt = 0; pt < 2; pt++) {
        #pragma unroll
        for (int l = 0; l < 2; l++) {
            int idx = tid + l * 256;
            int row = idx >> 3, ch = (idx & 7) * 8;
            cp16(sb + 4u * (pt * KVW + row * SKQ + (ch >> 1)),
                 Kg + (size_t)(pt * 64 + row) * DH + ch);
            cp16(sb + 4u * ((3 + pt) * KVW + row * SKQ + (ch >> 1)),
                 Vg + (size_t)(pt * 64 + row) * DH + ch);
        }
        if (tid < 64)
            mb3[pt * 64 + tid] = (mask[b * QLEN + pt * 64 + tid] == 0) ? -1e30f : 0.0f;
        CP_COMMIT();
    }

    float o[8][4] = {};
    float rm[2] = {-1e30f, -1e30f}, rl[2] = {0.0f, 0.0f};

    const int NT = QLEN / 64;   // 32
    int cur = 0, iss = 2;
    #pragma unroll 1
    for (int kt = 0; kt < NT; kt++) {
        if (kt + 2 < NT) { CP_WAIT(1); } else { CP_WAIT(0); }
        __syncthreads();    // tile kt visible; buffer iss free

        if (kt + 2 < NT) {
            const int kb2 = (kt + 2) * 64;
            #pragma unroll
            for (int l = 0; l < 2; l++) {
                int idx = tid + l * 256;
                int row = idx >> 3, ch = (idx & 7) * 8;
                cp16(sb + 4u * (iss * KVW + row * SKQ + (ch >> 1)),
                     Kg + (size_t)(kb2 + row) * DH + ch);
                cp16(sb + 4u * ((3 + iss) * KVW + row * SKQ + (ch >> 1)),
                     Vg + (size_t)(kb2 + row) * DH + ch);
            }
            if (tid < 64)
                mb3[iss * 64 + tid] = (mask[b * QLEN + kb2 + tid] == 0) ? -1e30f : 0.0f;
            CP_COMMIT();
        }

        const int kof = cur * KVW;
        const int vof = (3 + cur) * KVW;
        const float* mb = mb3 + cur * 64;

        // S = Q @ K^T  (warp: 16q x 64k), x4 B-fragment loads
        float s[8][4] = {};
        #pragma unroll
        for (int ks = 0; ks < 4; ks++) {
            #pragma unroll
            for (int ntp = 0; ntp < 4; ntp++) {
                uint32_t bf[4];
                ldsm_x4(bf, sb + 4u * (kof + (ntp * 16 + kx4row) * SKQ + ks * 8 + kx4sel));
                mma16(s[2 * ntp],     qf[ks], &bf[0]);
                mma16(s[2 * ntp + 1], qf[ks], &bf[2]);
            }
        }

        // mask add (vectorized float2 loads)
        #pragma unroll
        for (int nt = 0; nt < 8; nt++) {
            float2 bm = *(const float2*)&mb[nt * 8 + 2 * t];
            s[nt][0] += bm.x; s[nt][1] += bm.y;
            s[nt][2] += bm.x; s[nt][3] += bm.y;
        }

        // online softmax: max via shfl, exp via f16x2, row-sum via ones-MMA
        uint32_t p16[8][2];
        float mnew2[2], alpha2[2];
        #pragma unroll
        for (int r = 0; r < 2; r++) {
            float mx = -1e30f;
            #pragma unroll
            for (int nt = 0; nt < 8; nt++)
                mx = fmaxf(mx, fmaxf(s[nt][r * 2], s[nt][r * 2 + 1]));
            mx = fmaxf(mx, __shfl_xor_sync(0xffffffffu, mx, 1));
            mx = fmaxf(mx, __shfl_xor_sync(0xffffffffu, mx, 2));
            float mnew  = fmaxf(rm[r], mx);
            alpha2[r] = __expf(rm[r] - mnew);
            mnew2[r] = mnew;
            rm[r] = mnew;
            const float mli = mnew * L2E;
            #pragma unroll
            for (int nt = 0; nt < 8; nt++) {
                float t0 = fmaf(s[nt][r * 2],     L2E, -mli);
                float t1 = fmaf(s[nt][r * 2 + 1], L2E, -mli);
                p16[nt][r] = ex2_h2(h2(t0, t1));
            }
        }

        // Row sums via tensor core: c_rs = P @ ones  (exact fp32 accumulation)
        float c_rs[4] = {};
        uint32_t af[4][4];
        #pragma unroll
        for (int ks = 0; ks < 4; ks++) {
            af[ks][0] = p16[2 * ks][0];
            af[ks][1] = p16[2 * ks][1];
            af[ks][2] = p16[2 * ks + 1][0];
            af[ks][3] = p16[2 * ks + 1][1];
            mma16(c_rs, af[ks], ones_bf);
        }

        // rescale o while rs-mma completes
        #pragma unroll
        for (int r = 0; r < 2; r++) {
            #pragma unroll
            for (int nt = 0; nt < 8; nt++) {
                o[nt][r * 2]     *= alpha2[r];
                o[nt][r * 2 + 1] *= alpha2[r];
            }
        }
        rl[0] = rl[0] * alpha2[0] + c_rs[0];
        rl[1] = rl[1] * alpha2[1] + c_rs[2];

        // O += P @ V  (x4 trans V-fragment loads)
        #pragma unroll
        for (int ks = 0; ks < 4; ks++) {
            #pragma unroll
            for (int ntp = 0; ntp < 4; ntp++) {
                uint32_t bf[4];
                ldsm_x4t(bf, sb + 4u * (vof + (16 * ks + vrow) * SKQ + ntp * 8 + vx4c));
                mma16(o[2 * ntp],     af[ks], &bf[0]);
                mma16(o[2 * ntp + 1], af[ks], &bf[2]);
            }
        }

        cur = (cur == 2) ? 0 : cur + 1;
        iss = (iss == 2) ? 0 : iss + 1;
    }

    // Epilogue: ctx fp16 [b, t, h*64 + d]
    #pragma unroll
    for (int r = 0; r < 2; r++) {
        float inv = 1.0f / rl[r];
        int row = q0 + qw + g + r * 8;
        #pragma unroll
        for (int nt = 0; nt < 8; nt++) {
            uint32_t pv = h2(o[nt][r * 2] * inv, o[nt][r * 2 + 1] * inv);
            *(uint32_t*)&g_ctxh[(size_t)(b * QLEN + row) * DIM + h * DH + nt * 8 + 2 * t] = pv;
        }
    }
}

// ---------------------------------------------------------------------------
extern "C" void kernel_launch(void* const* d_in, const int* in_sizes, int n_in,
                              void* d_out, int out_size)
{
    const float* x    = (const float*)d_in[0];
    const int*   mask = (const int*)  d_in[1];
    const float* wq   = (const float*)d_in[2];
    const float* bq   = (const float*)d_in[3];
    const float* wk   = (const float*)d_in[4];
    const float* bk   = (const float*)d_in[5];
    const float* wv   = (const float*)d_in[6];
    const float* bv   = (const float*)d_in[7];
    const float* wo   = (const float*)d_in[8];
    const float* bo   = (const float*)d_in[9];
    float* out = (float*)d_out;

    __half* xh;
    cudaGetSymbolAddress((void**)&xh, g_xh);

    cudaFuncSetAttribute(gemm_qkv,
                         cudaFuncAttributeMaxDynamicSharedMemorySize, GEMM_SMEM_BYTES);
    cudaFuncSetAttribute(gemm_out,
                         cudaFuncAttributeMaxDynamicSharedMemorySize, GEMM_SMEM_BYTES);

    f2h_kernel<<<MTOT * DIM / 2048, 256>>>(x, xh);
    dim3 gw(DIM * DIM / 2048, 4);
    f2h_w_kernel<<<gw, 256>>>(wq, wk, wv, wo);

    dim3 gq(DIM / 128, MTOT / 128, 3);
    gemm_qkv<<<gq, 256, GEMM_SMEM_BYTES>>>(bq, bk, bv);

    dim3 ga(QLEN / 128, BSZ * NH);
    attn_h<<<ga, 256>>>(mask);

    dim3 go(DIM / 128, MTOT / 128);
    gemm_out<<<go, 256, GEMM_SMEM_BYTES>>>(bo, out);
}